// round 2
// baseline (speedup 1.0000x reference)
#include <cuda_runtime.h>
#include <cuda_bf16.h>
#include <cstdint>

// Problem constants
#define B    2
#define N    4096
#define QD   1024
#define CD   1024
#define H    8
#define DH   64
#define INNER 512       // H*DH
#define NK   4097       // N+1

// ---------------- scratch (device globals; no allocs allowed) ----------------
__device__ float g_q [B * N  * INNER];   // [B,N,INNER]
__device__ float g_k [B * NK * INNER];   // [B,NK,INNER]
__device__ float g_v [B * NK * INNER];   // [B,NK,INNER]
__device__ float g_ao[B * N  * INNER];   // attention output [B,N,INNER]
__device__ float g_pooled[B * QD];       // mean over N of x
__device__ unsigned char g_mask[B * NK];

// ---------------- mean pool: pooled[b][d] = mean_n x[b][n][d] ----------------
__global__ void pooled_kernel(const float* __restrict__ x) {
    int id = blockIdx.x * blockDim.x + threadIdx.x;
    if (id >= B * QD) return;
    int b = id / QD, d = id % QD;
    const float* p = x + (size_t)b * N * QD + d;
    float s = 0.f;
    for (int n = 0; n < N; n++) s += p[(size_t)n * QD];
    g_pooled[id] = s * (1.0f / N);
}

// ---------------- mask conversion (uint8 or int32 layout, auto-detect) -------
__global__ void mask_conv_kernel(const unsigned char* __restrict__ m) {
    __shared__ int any_nonzero;
    if (threadIdx.x == 0) any_nonzero = 0;
    __syncthreads();
    // If mask is int32 little-endian 0/1, every byte at idx%4 != 0 is zero.
    // For a random uint8 0/1 mask this fails with overwhelming probability.
    int local = 0;
    for (int i = threadIdx.x; i < 8192; i += blockDim.x)
        if ((i & 3) && m[i]) local = 1;
    if (local) atomicOr(&any_nonzero, 1);
    __syncthreads();
    bool is_u8 = (any_nonzero != 0);
    const int* mi = (const int*)m;
    for (int j = threadIdx.x; j < B * NK; j += blockDim.x)
        g_mask[j] = is_u8 ? (m[j] != 0) : (mi[j] != 0);
}

// ---------------- background rows: k_bg = pooled @ Wk_bg, v_bg likewise ------
__global__ void bg_kernel(const float* __restrict__ Wkbg,
                          const float* __restrict__ Wvbg) {
    int id = blockIdx.x * blockDim.x + threadIdx.x;
    if (id >= B * INNER) return;
    int b = id / INNER, o = id % INNER;
    float sk = 0.f, sv = 0.f;
    for (int k = 0; k < QD; k++) {
        float pv = g_pooled[b * QD + k];
        sk += pv * Wkbg[(size_t)k * INNER + o];
        sv += pv * Wvbg[(size_t)k * INNER + o];
    }
    size_t base = ((size_t)(b * NK + N)) * INNER + o;
    g_k[base] = sk;
    g_v[base] = sv;
}

// ---------------- SGEMM: C[M,Nn] = A[M,K] @ Bm[K,Nn] (row-major) -------------
// Output rows can be remapped for the k/v concat: orow = (r/rpb)*(rpb+pad)+r%rpb
// Optional bias added per output column.
__global__ __launch_bounds__(256)
void sgemm128(const float* __restrict__ A, const float* __restrict__ Bm,
              float* __restrict__ C, int M, int Nn, int K,
              int rowsPerBatch, int rowPad, const float* __restrict__ bias)
{
    __shared__ __align__(16) float As[16][128];
    __shared__ __align__(16) float Bs[16][128];
    int tx = threadIdx.x & 15, ty = threadIdx.x >> 4;
    int m0 = blockIdx.y * 128, n0 = blockIdx.x * 128;

    float acc[8][8];
    #pragma unroll
    for (int i = 0; i < 8; i++)
        #pragma unroll
        for (int j = 0; j < 8; j++) acc[i][j] = 0.f;

    for (int k0 = 0; k0 < K; k0 += 16) {
        #pragma unroll
        for (int i = 0; i < 8; i++) {
            int idx = threadIdx.x + i * 256;          // 0..2047  (128 rows x 16 k)
            int r = idx >> 4, c = idx & 15;
            As[c][r] = A[(size_t)(m0 + r) * K + k0 + c];
        }
        #pragma unroll
        for (int i = 0; i < 8; i++) {
            int idx = threadIdx.x + i * 256;          // 16 k-rows x 128 cols
            int r = idx >> 7, c = idx & 127;
            Bs[r][c] = Bm[(size_t)(k0 + r) * Nn + n0 + c];
        }
        __syncthreads();
        #pragma unroll
        for (int kk = 0; kk < 16; kk++) {
            float4 a0 = *(const float4*)&As[kk][ty * 8];
            float4 a1 = *(const float4*)&As[kk][ty * 8 + 4];
            float4 b0 = *(const float4*)&Bs[kk][tx * 8];
            float4 b1 = *(const float4*)&Bs[kk][tx * 8 + 4];
            float a[8] = {a0.x,a0.y,a0.z,a0.w,a1.x,a1.y,a1.z,a1.w};
            float bb[8] = {b0.x,b0.y,b0.z,b0.w,b1.x,b1.y,b1.z,b1.w};
            #pragma unroll
            for (int i = 0; i < 8; i++)
                #pragma unroll
                for (int j = 0; j < 8; j++)
                    acc[i][j] += a[i] * bb[j];
        }
        __syncthreads();
    }

    #pragma unroll
    for (int i = 0; i < 8; i++) {
        int rr = m0 + ty * 8 + i;
        int orow = rr;
        if (rowPad) orow = (rr / rowsPerBatch) * (rowsPerBatch + rowPad) + rr % rowsPerBatch;
        float* crow = C + (size_t)orow * Nn + n0 + tx * 8;
        #pragma unroll
        for (int j = 0; j < 8; j++) {
            float v = acc[i][j];
            if (bias) v += bias[n0 + tx * 8 + j];
            crow[j] = v;
        }
    }
}

// ---------------- flash attention: 64-query x 64-key tiles -------------------
// grid: (N/64, B*H), 256 threads (16x16), each thread 4x4 microtiles.
#define PADQ 65
#define ATTN_SMEM ((4 * 64 * PADQ + 64 * 16) * 4)

__global__ __launch_bounds__(256)
void attn_kernel() {
    extern __shared__ float sm[];
    float* Qs  = sm;                    // 64 x PADQ
    float* Ks  = Qs + 64 * PADQ;
    float* Vs  = Ks + 64 * PADQ;
    float* Ps  = Vs + 64 * PADQ;
    float* red = Ps + 64 * PADQ;        // 64 x 16

    int tid = threadIdx.x;
    int tx = tid & 15, ty = tid >> 4;
    int b = blockIdx.y >> 3, h = blockIdx.y & 7;
    int qi0 = blockIdx.x * 64;
    const float scale = 0.125f;         // DH^-0.5

    // load Q tile
    #pragma unroll
    for (int i = 0; i < 16; i++) {
        int idx = tid + i * 256;        // 4096 = 64x64
        int r = idx >> 6, d = idx & 63;
        Qs[r * PADQ + d] = g_q[((size_t)(b * N + qi0 + r)) * INNER + h * 64 + d];
    }

    float m_[4], l_[4], O[4][4];
    #pragma unroll
    for (int i = 0; i < 4; i++) {
        m_[i] = -1e30f; l_[i] = 0.f;
        #pragma unroll
        for (int j = 0; j < 4; j++) O[i][j] = 0.f;
    }

    for (int kt = 0; kt < 65; kt++) {
        int j0 = kt * 64;
        __syncthreads();   // protect prior-iter reads of Ks/Vs/Ps
        #pragma unroll
        for (int i = 0; i < 16; i++) {
            int idx = tid + i * 256;
            int r = idx >> 6, d = idx & 63;
            int jg = j0 + r;
            float kv = 0.f, vv = 0.f;
            if (jg < NK) {
                size_t base = ((size_t)(b * NK + jg)) * INNER + h * 64 + d;
                kv = g_k[base]; vv = g_v[base];
            }
            Ks[r * PADQ + d] = kv;
            Vs[r * PADQ + d] = vv;
        }
        __syncthreads();

        // S = Q K^T (4x4 per thread)
        float s[4][4];
        #pragma unroll
        for (int i = 0; i < 4; i++)
            #pragma unroll
            for (int j = 0; j < 4; j++) s[i][j] = 0.f;
        #pragma unroll 8
        for (int d = 0; d < 64; d++) {
            float a[4], kk[4];
            #pragma unroll
            for (int i = 0; i < 4; i++) a[i]  = Qs[(ty * 4 + i) * PADQ + d];
            #pragma unroll
            for (int j = 0; j < 4; j++) kk[j] = Ks[(tx * 4 + j) * PADQ + d];
            #pragma unroll
            for (int i = 0; i < 4; i++)
                #pragma unroll
                for (int j = 0; j < 4; j++)
                    s[i][j] += a[i] * kk[j];
        }
        // scale + mask
        bool ok[4];
        #pragma unroll
        for (int j = 0; j < 4; j++) {
            int jg = j0 + tx * 4 + j;
            ok[j] = (jg < NK) && (g_mask[b * NK + jg] != 0);
        }
        #pragma unroll
        for (int i = 0; i < 4; i++)
            #pragma unroll
            for (int j = 0; j < 4; j++)
                s[i][j] = ok[j] ? s[i][j] * scale : -1e30f;

        // row max: partial per thread, reduce via smem
        #pragma unroll
        for (int i = 0; i < 4; i++) {
            float tm = s[i][0];
            #pragma unroll
            for (int j = 1; j < 4; j++) tm = fmaxf(tm, s[i][j]);
            red[(ty * 4 + i) * 16 + tx] = tm;
        }
        __syncthreads();
        float mn[4], alpha[4];
        #pragma unroll
        for (int i = 0; i < 4; i++) {
            int row = ty * 4 + i;
            float mm = -1e30f;
            #pragma unroll
            for (int t = 0; t < 16; t++) mm = fmaxf(mm, red[row * 16 + t]);
            mn[i] = fmaxf(m_[i], mm);
            alpha[i] = __expf(m_[i] - mn[i]);
            m_[i] = mn[i];
        }
        __syncthreads();   // before reusing red for sums

        // P = exp(S - m), partial row sums, stage P in smem
        #pragma unroll
        for (int i = 0; i < 4; i++) {
            int row = ty * 4 + i;
            float ts = 0.f;
            #pragma unroll
            for (int j = 0; j < 4; j++) {
                float p = __expf(s[i][j] - mn[i]);
                ts += p;
                Ps[row * PADQ + tx * 4 + j] = p;
            }
            red[row * 16 + tx] = ts;
        }
        __syncthreads();
        #pragma unroll
        for (int i = 0; i < 4; i++) {
            int row = ty * 4 + i;
            float rs = 0.f;
            #pragma unroll
            for (int t = 0; t < 16; t++) rs += red[row * 16 + t];
            l_[i] = l_[i] * alpha[i] + rs;
            #pragma unroll
            for (int j = 0; j < 4; j++) O[i][j] *= alpha[i];
        }
        // O += P @ V
        #pragma unroll 8
        for (int c = 0; c < 64; c++) {
            float p[4], vv[4];
            #pragma unroll
            for (int i = 0; i < 4; i++) p[i]  = Ps[(ty * 4 + i) * PADQ + c];
            #pragma unroll
            for (int j = 0; j < 4; j++) vv[j] = Vs[c * PADQ + tx * 4 + j];
            #pragma unroll
            for (int i = 0; i < 4; i++)
                #pragma unroll
                for (int j = 0; j < 4; j++)
                    O[i][j] += p[i] * vv[j];
        }
    }

    #pragma unroll
    for (int i = 0; i < 4; i++) {
        float inv = 1.0f / l_[i];
        int row = qi0 + ty * 4 + i;
        #pragma unroll
        for (int j = 0; j < 4; j++)
            g_ao[((size_t)(b * N + row)) * INNER + h * 64 + tx * 4 + j] = O[i][j] * inv;
    }
}

// ---------------- launch ----------------
extern "C" void kernel_launch(void* const* d_in, const int* in_sizes, int n_in,
                              void* d_out, int out_size) {
    const float* x    = (const float*)d_in[0];
    const float* ctx  = (const float*)d_in[1];
    const unsigned char* mask = (const unsigned char*)d_in[2];
    const float* Wq   = (const float*)d_in[3];
    const float* Wk   = (const float*)d_in[4];
    const float* Wv   = (const float*)d_in[5];
    const float* Wkbg = (const float*)d_in[6];
    const float* Wvbg = (const float*)d_in[7];
    const float* Wout = (const float*)d_in[8];
    const float* bout = (const float*)d_in[9];
    float* out = (float*)d_out;

    float *qptr, *kptr, *vptr, *aoptr;
    cudaGetSymbolAddress((void**)&qptr,  g_q);
    cudaGetSymbolAddress((void**)&kptr,  g_k);
    cudaGetSymbolAddress((void**)&vptr,  g_v);
    cudaGetSymbolAddress((void**)&aoptr, g_ao);

    cudaFuncSetAttribute(attn_kernel,
                         cudaFuncAttributeMaxDynamicSharedMemorySize, ATTN_SMEM);

    mask_conv_kernel<<<1, 256>>>(mask);
    pooled_kernel<<<(B * QD + 255) / 256, 256>>>(x);

    // q = x @ Wq
    sgemm128<<<dim3(INNER / 128, (B * N) / 128), 256>>>(
        x, Wq, qptr, B * N, INNER, QD, B * N, 0, nullptr);
    // k[:, :N] = context @ Wk   (rows remapped into NK-strided buffer)
    sgemm128<<<dim3(INNER / 128, (B * N) / 128), 256>>>(
        ctx, Wk, kptr, B * N, INNER, CD, N, 1, nullptr);
    // v[:, :N] = context @ Wv
    sgemm128<<<dim3(INNER / 128, (B * N) / 128), 256>>>(
        ctx, Wv, vptr, B * N, INNER, CD, N, 1, nullptr);
    // background row (row N of k/v)
    bg_kernel<<<(B * INNER + 255) / 256, 256>>>(Wkbg, Wvbg);

    // attention
    attn_kernel<<<dim3(N / 64, B * H), 256, ATTN_SMEM>>>();

    // out = ao @ Wout + b_out
    sgemm128<<<dim3(QD / 128, (B * N) / 128), 256>>>(
        aoptr, Wout, out, B * N, QD, INNER, B * N, 0, bout);
}

// round 4
// speedup vs baseline: 1.9949x; 1.9949x over previous
#include <cuda_runtime.h>
#include <cuda_bf16.h>
#include <cstdint>

#define B     2
#define N     4096
#define QD    1024
#define CD    1024
#define H     8
#define DH    64
#define INNER 512
#define NK    4097
#define NKP   4224
typedef long long ll;
typedef __nv_bfloat16 bf;

// ---------------- device scratch ----------------
__device__ __align__(16) bf g_xs[2][B*N*QD];
__device__ __align__(16) bf g_cs[2][B*N*CD];
__device__ __align__(16) bf g_wq[2][QD*INNER];
__device__ __align__(16) bf g_wk[2][CD*INNER];
__device__ __align__(16) bf g_wv[2][CD*INNER];
__device__ __align__(16) bf g_wo[2][INNER*QD];
__device__ __align__(16) bf g_q [2][B*N*INNER];
__device__ __align__(16) bf g_k [2][B*NKP*INNER];
__device__ __align__(16) bf g_v [2][B*NKP*INNER];
__device__ __align__(16) bf g_vt[2][B*H*DH*NKP];
__device__ __align__(16) bf g_ao[2][B*N*INNER];
__device__ float g_S[(size_t)B*H*N*NKP];
__device__ __align__(16) bf g_P[2][(size_t)B*H*N*NKP];
__device__ float g_pooled[B*QD];
__device__ unsigned char g_maskp[B*NKP];

// ---------------- helpers ----------------
__device__ __forceinline__ uint32_t sm_u32(const void* p){
    uint32_t a;
    asm("{ .reg .u64 t; cvta.to.shared.u64 t, %1; cvt.u32.u64 %0, t; }" : "=r"(a) : "l"(p));
    return a;
}
__device__ __forceinline__ void ldmx4(uint32_t* r, uint32_t addr){
    asm volatile("ldmatrix.sync.aligned.m8n8.x4.shared.b16 {%0,%1,%2,%3}, [%4];"
        : "=r"(r[0]), "=r"(r[1]), "=r"(r[2]), "=r"(r[3]) : "r"(addr));
}
__device__ __forceinline__ void mma16816(float* d, const uint32_t* a, const uint32_t* b){
    asm volatile("mma.sync.aligned.m16n8k16.row.col.f32.bf16.bf16.f32 "
        "{%0,%1,%2,%3}, {%4,%5,%6,%7}, {%8,%9}, {%0,%1,%2,%3};"
        : "+f"(d[0]), "+f"(d[1]), "+f"(d[2]), "+f"(d[3])
        : "r"(a[0]), "r"(a[1]), "r"(a[2]), "r"(a[3]), "r"(b[0]), "r"(b[1]));
}
#define CP_ASYNC(dst, src) \
    asm volatile("cp.async.cg.shared.global [%0], [%1], 16;" :: "r"(dst), "l"(src))
#define CP_COMMIT() asm volatile("cp.async.commit_group;" ::: "memory")
#define CP_WAIT1()  asm volatile("cp.async.wait_group 1;" ::: "memory")
#define CP_WAIT0()  asm volatile("cp.async.wait_group 0;" ::: "memory")

// ---------------- small kernels ----------------
__global__ void pooled_kernel(const float* __restrict__ x){
    int id = blockIdx.x*256 + threadIdx.x;
    if (id >= B*QD) return;
    int b = id / QD, d = id % QD;
    const float* p = x + (size_t)b*N*QD + d;
    float s = 0.f;
    for (int n = 0; n < N; n++) s += p[(size_t)n*QD];
    g_pooled[id] = s * (1.0f/N);
}

__global__ void mask_conv_kernel(const unsigned char* __restrict__ m){
    __shared__ int anynz;
    if (threadIdx.x == 0) anynz = 0;
    __syncthreads();
    int loc = 0;
    for (int i = threadIdx.x; i < 8192; i += 256)
        if ((i & 3) && m[i]) loc = 1;
    if (loc) atomicOr(&anynz, 1);
    __syncthreads();
    bool u8 = (anynz != 0);
    const int* mi = (const int*)m;
    for (int j = threadIdx.x; j < B*NKP; j += 256){
        int b = j / NKP, w = j - b*NKP;
        g_maskp[j] = (w < NK) ? (u8 ? (m[b*NK+w] != 0) : (mi[b*NK+w] != 0)) : 0;
    }
}

__global__ void bg_kernel(const float* __restrict__ Wkbg, const float* __restrict__ Wvbg){
    int id = blockIdx.x*256 + threadIdx.x;
    if (id >= B*INNER) return;
    int b = id / INNER, o = id % INNER;
    float sk = 0.f, sv = 0.f;
    for (int k = 0; k < QD; k++){
        float pv = g_pooled[b*QD + k];
        sk += pv * Wkbg[(size_t)k*INNER + o];
        sv += pv * Wvbg[(size_t)k*INNER + o];
    }
    size_t base = (size_t)(b*NKP + N)*INNER + o;
    bf h;
    h = __float2bfloat16(sk); g_k[0][base] = h; g_k[1][base] = __float2bfloat16(sk - __bfloat162float(h));
    h = __float2bfloat16(sv); g_v[0][base] = h; g_v[1][base] = __float2bfloat16(sv - __bfloat162float(h));
}

__global__ void pack_split(const float4* __restrict__ src, bf* __restrict__ hi, bf* __restrict__ lo, int n4){
    int i = blockIdx.x*256 + threadIdx.x;
    if (i >= n4) return;
    float4 v = src[i];
    float vv[4] = {v.x, v.y, v.z, v.w};
    __nv_bfloat162 h2[2], l2[2];
    #pragma unroll
    for (int j = 0; j < 4; j++){
        bf h = __float2bfloat16(vv[j]);
        bf l = __float2bfloat16(vv[j] - __bfloat162float(h));
        ((bf*)h2)[j] = h; ((bf*)l2)[j] = l;
    }
    ((__nv_bfloat162*)hi)[i*2]   = h2[0]; ((__nv_bfloat162*)hi)[i*2+1] = h2[1];
    ((__nv_bfloat162*)lo)[i*2]   = l2[0]; ((__nv_bfloat162*)lo)[i*2+1] = l2[1];
}

__global__ void packT(const float* __restrict__ src, bf* __restrict__ hi, bf* __restrict__ lo, int R, int C){
    __shared__ float t[32][33];
    int c0 = blockIdx.x*32, r0 = blockIdx.y*32;
    for (int i = threadIdx.y; i < 32; i += 8)
        t[i][threadIdx.x] = src[(size_t)(r0+i)*C + c0 + threadIdx.x];
    __syncthreads();
    for (int i = threadIdx.y; i < 32; i += 8){
        float v = t[threadIdx.x][i];
        size_t o = (size_t)(c0+i)*R + r0 + threadIdx.x;
        bf h = __float2bfloat16(v);
        hi[o] = h; lo[o] = __float2bfloat16(v - __bfloat162float(h));
    }
}

__global__ void vtrans_kernel(){
    __shared__ bf t[2][32][33];
    int z = blockIdx.z, b = z >> 3, h = z & 7;
    int j0 = blockIdx.x*32, d0 = blockIdx.y*32;
    int tx = threadIdx.x, ty = threadIdx.y;
    #pragma unroll
    for (int s = 0; s < 2; s++)
        for (int i = ty; i < 32; i += 8)
            t[s][i][tx] = g_v[s][(size_t)(b*NKP + j0 + i)*INNER + h*64 + d0 + tx];
    __syncthreads();
    #pragma unroll
    for (int s = 0; s < 2; s++)
        for (int i = ty; i < 32; i += 8)
            g_vt[s][((size_t)z*DH + d0 + i)*NKP + j0 + tx] = t[s][tx][i];
}

// fast exp on FMA pipe (x <= 0)
__device__ __forceinline__ float fexp(float x){
    float t = fmaxf(x * 1.4426950409f, -120.f);
    float r = rintf(t);
    float f = t - r;
    float p = 1.33336e-3f;
    p = fmaf(p, f, 9.61812e-3f);
    p = fmaf(p, f, 5.55041e-2f);
    p = fmaf(p, f, 2.4022651e-1f);
    p = fmaf(p, f, 6.9314718e-1f);
    p = fmaf(p, f, 1.0f);
    return p * __int_as_float(((int)r + 127) << 23);
}

__global__ __launch_bounds__(256) void softmax_kernel(){
    __shared__ float redm[8], reds[8];
    size_t row = blockIdx.x;
    int b = (int)(row >> 15);
    const float* Sr = g_S + row*NKP;
    int tid = threadIdx.x, wid = tid >> 5, lane = tid & 31;
    float4 v[5];
    float mx = -1e30f;
    #pragma unroll
    for (int i = 0; i < 5; i++){
        int idx = tid + i*256;
        if (idx < 1056){
            float4 s4 = ((const float4*)Sr)[idx];
            uchar4 mk = ((const uchar4*)(g_maskp + b*NKP))[idx];
            s4.x = mk.x ? s4.x*0.125f : -1e30f;
            s4.y = mk.y ? s4.y*0.125f : -1e30f;
            s4.z = mk.z ? s4.z*0.125f : -1e30f;
            s4.w = mk.w ? s4.w*0.125f : -1e30f;
            v[i] = s4;
            mx = fmaxf(mx, fmaxf(fmaxf(s4.x, s4.y), fmaxf(s4.z, s4.w)));
        }
    }
    #pragma unroll
    for (int o = 16; o; o >>= 1) mx = fmaxf(mx, __shfl_xor_sync(~0u, mx, o));
    if (lane == 0) redm[wid] = mx;
    __syncthreads();
    mx = redm[0];
    #pragma unroll
    for (int w = 1; w < 8; w++) mx = fmaxf(mx, redm[w]);

    float sum = 0.f;
    #pragma unroll
    for (int i = 0; i < 5; i++){
        int idx = tid + i*256;
        if (idx < 1056){
            float4 e;
            e.x = fexp(v[i].x - mx); e.y = fexp(v[i].y - mx);
            e.z = fexp(v[i].z - mx); e.w = fexp(v[i].w - mx);
            v[i] = e;
            sum += e.x + e.y + e.z + e.w;
        }
    }
    #pragma unroll
    for (int o = 16; o; o >>= 1) sum += __shfl_xor_sync(~0u, sum, o);
    if (lane == 0) reds[wid] = sum;
    __syncthreads();
    sum = reds[0];
    #pragma unroll
    for (int w = 1; w < 8; w++) sum += reds[w];
    float inv = 1.0f / sum;

    bf* Ph = g_P[0] + row*NKP;
    bf* Pl = g_P[1] + row*NKP;
    #pragma unroll
    for (int i = 0; i < 5; i++){
        int idx = tid + i*256;
        if (idx < 1056){
            float pv[4] = {v[i].x*inv, v[i].y*inv, v[i].z*inv, v[i].w*inv};
            __nv_bfloat162 h2[2], l2[2];
            #pragma unroll
            for (int j = 0; j < 4; j++){
                bf h = __float2bfloat16(pv[j]);
                ((bf*)h2)[j] = h;
                ((bf*)l2)[j] = __float2bfloat16(pv[j] - __bfloat162float(h));
            }
            ((__nv_bfloat162*)Ph)[idx*2]   = h2[0]; ((__nv_bfloat162*)Ph)[idx*2+1] = h2[1];
            ((__nv_bfloat162*)Pl)[idx*2]   = l2[0]; ((__nv_bfloat162*)Pl)[idx*2+1] = l2[1];
        }
    }
}

// ---------------- warp-mma split-bf16 GEMM ----------------
// C[M,Nt] = A[M,K] @ B[Nt,K]^T ; A,B bf16 hi/lo row-major [*,K]; fp32 accum.
struct GemmArgs {
    const bf *Ah, *Al, *Bh, *Bl;
    int K, lda, ldb;
    ll sAb, sAh, sBb, sBh;
    float* Cf; const float* bias;
    bf *Ch, *Cl;
    ll sCb, sCh; int ldc, remap;
};

template<int NTILE>
__global__ __launch_bounds__(256, 1) void gemm_mma(GemmArgs g){
    constexpr int KC = 32, KPAD = 40;                 // 80B padded rows
    constexpr int WGM = (NTILE == 128) ? 2 : 4;
    constexpr int WGN = 8 / WGM;
    constexpr int WM = 128 / WGM;                     // 64 or 32
    constexpr int WN = NTILE / WGN;                   // 32
    constexpr int MT = WM / 16, NT = WN / 8;          // (4,4) or (2,4)
    constexpr int ASZ = 128 * KPAD * 2;               // bytes, one A tile
    constexpr int BSZ = NTILE * KPAD * 2;
    constexpr int STAGE = 2*ASZ + 2*BSZ;
    constexpr int TOT = 1024 + NTILE*8;               // 16B units per chunk

    extern __shared__ __align__(16) char smem[];
    uint32_t sbase = sm_u32(smem);

    int tid = threadIdx.x, wid = tid >> 5, lane = tid & 31;
    int wm = wid % WGM, wn = wid / WGM;

    int zb = blockIdx.z >> 3, zh = blockIdx.z & 7;
    const bf* pAh = g.Ah + zb*g.sAb + zh*g.sAh + (ll)blockIdx.y*128*g.lda;
    const bf* pAl = g.Al + zb*g.sAb + zh*g.sAh + (ll)blockIdx.y*128*g.lda;
    const bf* pBh = g.Bh + zb*g.sBb + zh*g.sBh + (ll)blockIdx.x*NTILE*g.ldb;
    const bf* pBl = g.Bl + zb*g.sBb + zh*g.sBh + (ll)blockIdx.x*NTILE*g.ldb;

    float acc[MT][NT][4];
    #pragma unroll
    for (int i = 0; i < MT; i++)
        #pragma unroll
        for (int j = 0; j < NT; j++)
            #pragma unroll
            for (int e = 0; e < 4; e++) acc[i][j][e] = 0.f;

    int nch = g.K / KC;

    auto load_chunk = [&](int c){
        int s = c & 1, k0 = c * KC;
        uint32_t st = sbase + s*STAGE;
        #pragma unroll 2
        for (int u = tid; u < TOT; u += 256){
            const bf* src; uint32_t doff; int rel, ld;
            if (u < 512)            { rel = u;              src = pAh; doff = 0;          ld = g.lda; }
            else if (u < 1024)      { rel = u - 512;        src = pAl; doff = ASZ;        ld = g.lda; }
            else if (u < 1024+NTILE*4){ rel = u - 1024;     src = pBh; doff = 2*ASZ;      ld = g.ldb; }
            else                    { rel = u-1024-NTILE*4; src = pBl; doff = 2*ASZ+BSZ;  ld = g.ldb; }
            int r = rel >> 2, sg = rel & 3;
            const bf* gsrc = src + (ll)r*ld + k0 + sg*8;
            uint32_t sdst = st + doff + (uint32_t)(r*KPAD + sg*8)*2;
            CP_ASYNC(sdst, gsrc);
        }
        CP_COMMIT();
    };

    load_chunk(0);
    for (int c = 0; c < nch; c++){
        if (c + 1 < nch){ load_chunk(c + 1); CP_WAIT1(); }
        else            { CP_WAIT0(); }
        __syncthreads();

        uint32_t stg = sbase + (c & 1)*STAGE;
        #pragma unroll
        for (int ks = 0; ks < 2; ks++){
            int kb = ks * 16;
            uint32_t aH[MT][4], aL[MT][4];
            #pragma unroll
            for (int mt = 0; mt < MT; mt++){
                int row = wm*WM + mt*16 + (lane & 15);
                int col = kb + (lane >> 4)*8;
                uint32_t ad = stg + (uint32_t)(row*KPAD + col)*2;
                ldmx4(aH[mt], ad);
                ldmx4(aL[mt], ad + ASZ);
            }
            #pragma unroll
            for (int p = 0; p < NT/2; p++){
                int gg = lane >> 3, ii = lane & 7;
                int row = wn*WN + p*16 + (gg >> 1)*8 + ii;
                int col = kb + (gg & 1)*8;
                uint32_t bd = stg + 2*ASZ + (uint32_t)(row*KPAD + col)*2;
                uint32_t bH[4], bL[4];
                ldmx4(bH, bd);
                ldmx4(bL, bd + BSZ);
                #pragma unroll
                for (int mt = 0; mt < MT; mt++){
                    mma16816(acc[mt][2*p],   aH[mt], bH);
                    mma16816(acc[mt][2*p],   aH[mt], bL);
                    mma16816(acc[mt][2*p],   aL[mt], bH);
                    mma16816(acc[mt][2*p+1], aH[mt], bH + 2);
                    mma16816(acc[mt][2*p+1], aH[mt], bL + 2);
                    mma16816(acc[mt][2*p+1], aL[mt], bH + 2);
                }
            }
        }
        __syncthreads();
    }

    // epilogue
    ll zoff = zb*g.sCb + zh*g.sCh;
    int ncb = blockIdx.x*NTILE + wn*WN;
    #pragma unroll
    for (int mt = 0; mt < MT; mt++){
        #pragma unroll
        for (int hf = 0; hf < 2; hf++){
            int row = blockIdx.y*128 + wm*WM + mt*16 + (lane >> 2) + hf*8;
            ll orow = (ll)(row >> 12)*g.remap + (row & 4095);
            ll basei = zoff + orow*(ll)g.ldc + ncb;
            #pragma unroll
            for (int nt = 0; nt < NT; nt++){
                int cl = nt*8 + (lane & 3)*2;
                float v0 = acc[mt][nt][hf*2], v1 = acc[mt][nt][hf*2+1];
                if (g.Cf){
                    if (g.bias){ v0 += g.bias[ncb + cl]; v1 += g.bias[ncb + cl + 1]; }
                    float2 f2; f2.x = v0; f2.y = v1;
                    *(float2*)(g.Cf + basei + cl) = f2;
                } else {
                    bf h0 = __float2bfloat16(v0), h1 = __float2bfloat16(v1);
                    __nv_bfloat162 hh, ll2;
                    hh.x = h0; hh.y = h1;
                    ll2.x = __float2bfloat16(v0 - __bfloat162float(h0));
                    ll2.y = __float2bfloat16(v1 - __bfloat162float(h1));
                    *(__nv_bfloat162*)(g.Ch + basei + cl) = hh;
                    *(__nv_bfloat162*)(g.Cl + basei + cl) = ll2;
                }
            }
        }
    }
}

// ---------------- launch ----------------
extern "C" void kernel_launch(void* const* d_in, const int* in_sizes, int n_in,
                              void* d_out, int out_size){
    const float* x    = (const float*)d_in[0];
    const float* ctx  = (const float*)d_in[1];
    const unsigned char* mask = (const unsigned char*)d_in[2];
    const float* Wq   = (const float*)d_in[3];
    const float* Wk   = (const float*)d_in[4];
    const float* Wv   = (const float*)d_in[5];
    const float* Wkbg = (const float*)d_in[6];
    const float* Wvbg = (const float*)d_in[7];
    const float* Wout = (const float*)d_in[8];
    const float* bout = (const float*)d_in[9];
    float* out = (float*)d_out;

    bf *xs, *cs, *wq, *wk, *wv, *wo, *q, *k, *v, *vt, *ao, *P;
    float* S;
    cudaGetSymbolAddress((void**)&xs, g_xs);
    cudaGetSymbolAddress((void**)&cs, g_cs);
    cudaGetSymbolAddress((void**)&wq, g_wq);
    cudaGetSymbolAddress((void**)&wk, g_wk);
    cudaGetSymbolAddress((void**)&wv, g_wv);
    cudaGetSymbolAddress((void**)&wo, g_wo);
    cudaGetSymbolAddress((void**)&q,  g_q);
    cudaGetSymbolAddress((void**)&k,  g_k);
    cudaGetSymbolAddress((void**)&v,  g_v);
    cudaGetSymbolAddress((void**)&vt, g_vt);
    cudaGetSymbolAddress((void**)&ao, g_ao);
    cudaGetSymbolAddress((void**)&S,  g_S);
    cudaGetSymbolAddress((void**)&P,  g_P);
    const size_t XSZ = (size_t)B*N*QD, QSZ = (size_t)B*N*INNER;
    const size_t KSZ = (size_t)B*NKP*INNER, VTSZ = (size_t)B*H*DH*NKP;
    const size_t WSZ = (size_t)QD*INNER, PSZ = (size_t)B*H*N*NKP;

    const int SM128 = 2*(2*128*40*2 + 2*128*40*2);   // 81920
    const int SM64  = 2*(2*128*40*2 + 2*64*40*2);    // 61440
    cudaFuncSetAttribute(gemm_mma<128>, cudaFuncAttributeMaxDynamicSharedMemorySize, SM128);
    cudaFuncSetAttribute(gemm_mma<64>,  cudaFuncAttributeMaxDynamicSharedMemorySize, SM64);

    mask_conv_kernel<<<1, 256>>>(mask);
    pooled_kernel<<<(B*QD + 255)/256, 256>>>(x);
    pack_split<<<(int)((XSZ/4 + 255)/256), 256>>>((const float4*)x,   xs, xs + XSZ, (int)(XSZ/4));
    pack_split<<<(int)((XSZ/4 + 255)/256), 256>>>((const float4*)ctx, cs, cs + XSZ, (int)(XSZ/4));
    packT<<<dim3(INNER/32, QD/32),    dim3(32, 8)>>>(Wq,   wq, wq + WSZ, QD, INNER);
    packT<<<dim3(INNER/32, QD/32),    dim3(32, 8)>>>(Wk,   wk, wk + WSZ, CD, INNER);
    packT<<<dim3(INNER/32, QD/32),    dim3(32, 8)>>>(Wv,   wv, wv + WSZ, CD, INNER);
    packT<<<dim3(QD/32,    INNER/32), dim3(32, 8)>>>(Wout, wo, wo + WSZ, INNER, QD);
    bg_kernel<<<(B*INNER + 255)/256, 256>>>(Wkbg, Wvbg);

    GemmArgs a;
    // q = x @ Wq
    a = { xs, xs + XSZ, wq, wq + WSZ, QD, QD, QD, 0, 0, 0, 0,
          nullptr, nullptr, q, q + QSZ, 0, 0, INNER, 4096 };
    gemm_mma<128><<<dim3(INNER/128, (B*N)/128, 1), 256, SM128>>>(a);
    // k = ctx @ Wk (rows remapped to NKP stride)
    a = { cs, cs + XSZ, wk, wk + WSZ, CD, CD, CD, 0, 0, 0, 0,
          nullptr, nullptr, k, k + KSZ, 0, 0, INNER, NKP };
    gemm_mma<128><<<dim3(INNER/128, (B*N)/128, 1), 256, SM128>>>(a);
    // v = ctx @ Wv
    a = { cs, cs + XSZ, wv, wv + WSZ, CD, CD, CD, 0, 0, 0, 0,
          nullptr, nullptr, v, v + KSZ, 0, 0, INNER, NKP };
    gemm_mma<128><<<dim3(INNER/128, (B*N)/128, 1), 256, SM128>>>(a);
    // S = q @ k^T (batched over b,h)
    a = { q, q + QSZ, k, k + KSZ, 64, INNER, INNER,
          (ll)N*INNER, 64, (ll)NKP*INNER, 64,
          S, nullptr, nullptr, nullptr, (ll)H*N*NKP, (ll)N*NKP, NKP, 4096 };
    gemm_mma<128><<<dim3(NKP/128, N/128, B*H), 256, SM128>>>(a);
    // softmax -> P hi/lo
    softmax_kernel<<<B*H*N, 256>>>();
    // vT
    vtrans_kernel<<<dim3(NKP/32, DH/32, B*H), dim3(32, 8)>>>();
    // ao = P @ V (batched)
    a = { P, P + PSZ, vt, vt + VTSZ, NKP, NKP, NKP,
          (ll)H*N*NKP, (ll)N*NKP, (ll)H*DH*NKP, (ll)DH*NKP,
          nullptr, nullptr, ao, ao + QSZ, (ll)N*INNER, 64, INNER, 4096 };
    gemm_mma<64><<<dim3(1, N/128, B*H), 256, SM64>>>(a);
    // out = ao @ Wout + b
    a = { ao, ao + QSZ, wo, wo + WSZ, INNER, INNER, INNER, 0, 0, 0, 0,
          out, bout, nullptr, nullptr, 0, 0, QD, 4096 };
    gemm_mma<128><<<dim3(QD/128, (B*N)/128, 1), 256, SM128>>>(a);
}

// round 5
// speedup vs baseline: 2.4909x; 1.2486x over previous
#include <cuda_runtime.h>
#include <cuda_bf16.h>
#include <cstdint>

#define B     2
#define N     4096
#define QD    1024
#define CD    1024
#define H     8
#define DH    64
#define INNER 512
#define NK    4097
#define NKP   4224
typedef long long ll;
typedef __nv_bfloat16 bf;

// ---------------- device scratch ----------------
__device__ __align__(16) bf g_xs[2][B*N*QD];
__device__ __align__(16) bf g_cs[2][B*N*CD];
__device__ __align__(16) bf g_wq[2][QD*INNER];
__device__ __align__(16) bf g_wk[2][CD*INNER];
__device__ __align__(16) bf g_wv[2][CD*INNER];
__device__ __align__(16) bf g_wo[2][INNER*QD];
__device__ __align__(16) bf g_q [2][B*N*INNER];
__device__ __align__(16) bf g_k [2][B*NKP*INNER];
__device__ __align__(16) bf g_v [2][B*NKP*INNER];
__device__ __align__(16) bf g_vt[2][B*H*DH*NKP];
__device__ __align__(16) bf g_ao[2][B*N*INNER];
__device__ float g_pooled[B*QD];
__device__ __align__(16) unsigned char g_maskp[B*NKP];

// ---------------- helpers ----------------
__device__ __forceinline__ uint32_t sm_u32(const void* p){
    uint32_t a;
    asm("{ .reg .u64 t; cvta.to.shared.u64 t, %1; cvt.u32.u64 %0, t; }" : "=r"(a) : "l"(p));
    return a;
}
__device__ __forceinline__ void ldmx4(uint32_t* r, uint32_t addr){
    asm volatile("ldmatrix.sync.aligned.m8n8.x4.shared.b16 {%0,%1,%2,%3}, [%4];"
        : "=r"(r[0]), "=r"(r[1]), "=r"(r[2]), "=r"(r[3]) : "r"(addr));
}
__device__ __forceinline__ void mma16816(float* d, const uint32_t* a, const uint32_t* b){
    asm volatile("mma.sync.aligned.m16n8k16.row.col.f32.bf16.bf16.f32 "
        "{%0,%1,%2,%3}, {%4,%5,%6,%7}, {%8,%9}, {%0,%1,%2,%3};"
        : "+f"(d[0]), "+f"(d[1]), "+f"(d[2]), "+f"(d[3])
        : "r"(a[0]), "r"(a[1]), "r"(a[2]), "r"(a[3]), "r"(b[0]), "r"(b[1]));
}
#define CP_ASYNC(dst, src) \
    asm volatile("cp.async.cg.shared.global [%0], [%1], 16;" :: "r"(dst), "l"(src))
#define CP_COMMIT() asm volatile("cp.async.commit_group;" ::: "memory")
#define CP_WAIT1()  asm volatile("cp.async.wait_group 1;" ::: "memory")
#define CP_WAIT0()  asm volatile("cp.async.wait_group 0;" ::: "memory")

__device__ __forceinline__ uint32_t packbf(float a, float b){
    __nv_bfloat162 t; t.x = __float2bfloat16(a); t.y = __float2bfloat16(b);
    return *(uint32_t*)&t;
}
__device__ __forceinline__ uint32_t packbf_lo(float a, float b, uint32_t hi){
    __nv_bfloat162 h = *(__nv_bfloat162*)&hi;
    return packbf(a - __bfloat162float(h.x), b - __bfloat162float(h.y));
}
// fast exp on FMA pipe (finite args; result for very negative x ~ 0)
__device__ __forceinline__ float fexp(float x){
    float t = fmaxf(x * 1.4426950409f, -120.f);
    float r = rintf(t);
    float f = t - r;
    float p = 1.33336e-3f;
    p = fmaf(p, f, 9.61812e-3f);
    p = fmaf(p, f, 5.55041e-2f);
    p = fmaf(p, f, 2.4022651e-1f);
    p = fmaf(p, f, 6.9314718e-1f);
    p = fmaf(p, f, 1.0f);
    return p * __int_as_float(((int)r + 127) << 23);
}

// ---------------- small kernels ----------------
__global__ void pooled_kernel(const float* __restrict__ x){
    int id = blockIdx.x*256 + threadIdx.x;
    if (id >= B*QD) return;
    int b = id / QD, d = id % QD;
    const float* p = x + (size_t)b*N*QD + d;
    float s = 0.f;
    for (int n = 0; n < N; n++) s += p[(size_t)n*QD];
    g_pooled[id] = s * (1.0f/N);
}

__global__ void mask_conv_kernel(const unsigned char* __restrict__ m){
    __shared__ int anynz;
    if (threadIdx.x == 0) anynz = 0;
    __syncthreads();
    int loc = 0;
    for (int i = threadIdx.x; i < 8192; i += 256)
        if ((i & 3) && m[i]) loc = 1;
    if (loc) atomicOr(&anynz, 1);
    __syncthreads();
    bool u8 = (anynz != 0);
    const int* mi = (const int*)m;
    for (int j = threadIdx.x; j < B*NKP; j += 256){
        int b = j / NKP, w = j - b*NKP;
        g_maskp[j] = (w < NK) ? (u8 ? (m[b*NK+w] != 0) : (mi[b*NK+w] != 0)) : 0;
    }
}

// zero the never-written pad rows of k/v (rows N+1..NKP-1 per batch)
__global__ void zero_pad_kernel(){
    int id = blockIdx.x*256 + threadIdx.x;          // covers B*(NKP-N-1)*INNER
    int tot = B*(NKP - N - 1)*INNER;
    if (id >= tot) return;
    int b = id / ((NKP - N - 1)*INNER);
    int rem = id - b*(NKP - N - 1)*INNER;
    int r = rem / INNER, o = rem - r*INNER;
    size_t base = (size_t)(b*NKP + N + 1 + r)*INNER + o;
    g_k[0][base] = __float2bfloat16(0.f); g_k[1][base] = __float2bfloat16(0.f);
    g_v[0][base] = __float2bfloat16(0.f); g_v[1][base] = __float2bfloat16(0.f);
}

__global__ void bg_kernel(const float* __restrict__ Wkbg, const float* __restrict__ Wvbg){
    int id = blockIdx.x*256 + threadIdx.x;
    if (id >= B*INNER) return;
    int b = id / INNER, o = id % INNER;
    float sk = 0.f, sv = 0.f;
    for (int k = 0; k < QD; k++){
        float pv = g_pooled[b*QD + k];
        sk += pv * Wkbg[(size_t)k*INNER + o];
        sv += pv * Wvbg[(size_t)k*INNER + o];
    }
    size_t base = (size_t)(b*NKP + N)*INNER + o;
    bf h;
    h = __float2bfloat16(sk); g_k[0][base] = h; g_k[1][base] = __float2bfloat16(sk - __bfloat162float(h));
    h = __float2bfloat16(sv); g_v[0][base] = h; g_v[1][base] = __float2bfloat16(sv - __bfloat162float(h));
}

__global__ void pack_split(const float4* __restrict__ src, bf* __restrict__ hi, bf* __restrict__ lo, int n4){
    int i = blockIdx.x*256 + threadIdx.x;
    if (i >= n4) return;
    float4 v = src[i];
    float vv[4] = {v.x, v.y, v.z, v.w};
    __nv_bfloat162 h2[2], l2[2];
    #pragma unroll
    for (int j = 0; j < 4; j++){
        bf h = __float2bfloat16(vv[j]);
        bf l = __float2bfloat16(vv[j] - __bfloat162float(h));
        ((bf*)h2)[j] = h; ((bf*)l2)[j] = l;
    }
    ((__nv_bfloat162*)hi)[i*2]   = h2[0]; ((__nv_bfloat162*)hi)[i*2+1] = h2[1];
    ((__nv_bfloat162*)lo)[i*2]   = l2[0]; ((__nv_bfloat162*)lo)[i*2+1] = l2[1];
}

__global__ void packT(const float* __restrict__ src, bf* __restrict__ hi, bf* __restrict__ lo, int R, int C){
    __shared__ float t[32][33];
    int c0 = blockIdx.x*32, r0 = blockIdx.y*32;
    for (int i = threadIdx.y; i < 32; i += 8)
        t[i][threadIdx.x] = src[(size_t)(r0+i)*C + c0 + threadIdx.x];
    __syncthreads();
    for (int i = threadIdx.y; i < 32; i += 8){
        float v = t[threadIdx.x][i];
        size_t o = (size_t)(c0+i)*R + r0 + threadIdx.x;
        bf h = __float2bfloat16(v);
        hi[o] = h; lo[o] = __float2bfloat16(v - __bfloat162float(h));
    }
}

__global__ void vtrans_kernel(){
    __shared__ bf t[2][32][33];
    int z = blockIdx.z, b = z >> 3, h = z & 7;
    int j0 = blockIdx.x*32, d0 = blockIdx.y*32;
    int tx = threadIdx.x, ty = threadIdx.y;
    #pragma unroll
    for (int s = 0; s < 2; s++)
        for (int i = ty; i < 32; i += 8)
            t[s][i][tx] = g_v[s][(size_t)(b*NKP + j0 + i)*INNER + h*64 + d0 + tx];
    __syncthreads();
    #pragma unroll
    for (int s = 0; s < 2; s++)
        for (int i = ty; i < 32; i += 8)
            g_vt[s][((size_t)z*DH + d0 + i)*NKP + j0 + tx] = t[s][tx][i];
}

// ---------------- fused flash attention ----------------
// CTA: 64 queries x (loop 66 tiles of 64 keys), 4 warps, each warp 16 rows.
// smem layout (bf16 tiles 64 x 72, 9216 B each):
//   Qh @0, Ql @9216, stages @18432 + s*36864 { Kh, Kl, Vth, Vtl }, mask @92160 + s*64
#define FSP 72
#define FTB (64*FSP*2)          // 9216
#define FSTG (4*FTB)            // 36864
#define FSMEM (2*FTB + 2*FSTG + 128)

__global__ __launch_bounds__(128, 2) void flash_kernel(){
    extern __shared__ __align__(16) char fsm[];
    const int tid = threadIdx.x, wid = tid >> 5, lane = tid & 31;
    const int z = blockIdx.y, b = z >> 3, h = z & 7;
    const int q0 = blockIdx.x*64;
    uint32_t sb = sm_u32(fsm);
    const uint32_t oQ = 0, oS = 2*FTB, oM = 2*FTB + 2*FSTG;

    const bf* Qg[2] = { g_q[0] + ((size_t)(b*N + q0))*INNER + h*64,
                        g_q[1] + ((size_t)(b*N + q0))*INNER + h*64 };
    const bf* Kg[2] = { g_k[0] + (size_t)b*NKP*INNER + h*64,
                        g_k[1] + (size_t)b*NKP*INNER + h*64 };
    const bf* Vg[2] = { g_vt[0] + (size_t)z*DH*NKP,
                        g_vt[1] + (size_t)z*DH*NKP };
    const unsigned char* Mg = g_maskp + b*NKP;

    auto load_stage = [&](int t){
        int j0 = t*64;
        uint32_t st = sb + oS + (t & 1)*FSTG;
        #pragma unroll 4
        for (int u = tid; u < 2048; u += 128){
            int tile = u >> 9, r = (u >> 3) & 63, sg = u & 7;
            const bf* src;
            if (tile == 0)      src = Kg[0] + (size_t)(j0 + r)*INNER + sg*8;
            else if (tile == 1) src = Kg[1] + (size_t)(j0 + r)*INNER + sg*8;
            else if (tile == 2) src = Vg[0] + (size_t)r*NKP + j0 + sg*8;
            else                src = Vg[1] + (size_t)r*NKP + j0 + sg*8;
            CP_ASYNC(st + tile*FTB + (uint32_t)(r*FSP + sg*8)*2, src);
        }
        if (tid < 4)
            CP_ASYNC(sb + oM + (t & 1)*64 + tid*16, Mg + j0 + tid*16);
    };

    // prologue: Q + stage0 (group A), stage1 (group B)
    #pragma unroll 4
    for (int u = tid; u < 1024; u += 128){
        int half = u >> 9, r = (u >> 3) & 63, sg = u & 7;
        CP_ASYNC(sb + oQ + half*FTB + (uint32_t)(r*FSP + sg*8)*2,
                 Qg[half] + (size_t)r*INNER + sg*8);
    }
    load_stage(0); CP_COMMIT();
    load_stage(1); CP_COMMIT();

    uint32_t aQh[4][4], aQl[4][4];
    float m0 = -1e30f, m1 = -1e30f, l0 = 0.f, l1 = 0.f;
    float o[8][4];
    #pragma unroll
    for (int i = 0; i < 8; i++){ o[i][0]=0.f; o[i][1]=0.f; o[i][2]=0.f; o[i][3]=0.f; }

    const int gg = lane >> 3, ii = lane & 7, tq = lane & 3;

    for (int t = 0; t < 66; t++){
        if (t < 64) CP_WAIT1(); else CP_WAIT0();
        __syncthreads();

        if (t == 0){
            int row = wid*16 + (lane & 15);
            int col = (lane >> 4)*8;
            #pragma unroll
            for (int ks = 0; ks < 4; ks++){
                uint32_t ad = sb + oQ + (uint32_t)(row*FSP + ks*16 + col)*2;
                ldmx4(aQh[ks], ad);
                ldmx4(aQl[ks], ad + FTB);
            }
        }

        uint32_t st = sb + oS + (t & 1)*FSTG;

        // S = Qh Kh + Qh Kl + Ql Kh
        float s[8][4];
        #pragma unroll
        for (int i = 0; i < 8; i++){ s[i][0]=0.f; s[i][1]=0.f; s[i][2]=0.f; s[i][3]=0.f; }
        #pragma unroll
        for (int ks = 0; ks < 4; ks++){
            #pragma unroll
            for (int p = 0; p < 4; p++){
                int rn = p*16 + (gg >> 1)*8 + ii;
                int ck = ks*16 + (gg & 1)*8;
                uint32_t off = (uint32_t)(rn*FSP + ck)*2;
                uint32_t bh[4], bl[4];
                ldmx4(bh, st + off);
                ldmx4(bl, st + FTB + off);
                mma16816(s[2*p],   aQh[ks], bh);
                mma16816(s[2*p],   aQh[ks], bl);
                mma16816(s[2*p],   aQl[ks], bh);
                mma16816(s[2*p+1], aQh[ks], bh + 2);
                mma16816(s[2*p+1], aQh[ks], bl + 2);
                mma16816(s[2*p+1], aQl[ks], bh + 2);
            }
        }

        // mask + scale
        const unsigned char* mk = (const unsigned char*)(fsm + oM + (t & 1)*64);
        #pragma unroll
        for (int nt = 0; nt < 8; nt++){
            int c0 = nt*8 + tq*2;
            bool k0 = mk[c0] != 0, k1 = mk[c0+1] != 0;
            s[nt][0] = k0 ? s[nt][0]*0.125f : -1e30f;
            s[nt][1] = k1 ? s[nt][1]*0.125f : -1e30f;
            s[nt][2] = k0 ? s[nt][2]*0.125f : -1e30f;
            s[nt][3] = k1 ? s[nt][3]*0.125f : -1e30f;
        }

        // online softmax (rows g and g+8; cols span lanes tq via shfl 1,2)
        float r0 = -1e30f, r1 = -1e30f;
        #pragma unroll
        for (int nt = 0; nt < 8; nt++){
            r0 = fmaxf(r0, fmaxf(s[nt][0], s[nt][1]));
            r1 = fmaxf(r1, fmaxf(s[nt][2], s[nt][3]));
        }
        r0 = fmaxf(r0, __shfl_xor_sync(~0u, r0, 1));
        r0 = fmaxf(r0, __shfl_xor_sync(~0u, r0, 2));
        r1 = fmaxf(r1, __shfl_xor_sync(~0u, r1, 1));
        r1 = fmaxf(r1, __shfl_xor_sync(~0u, r1, 2));
        float mn0 = fmaxf(m0, r0), mn1 = fmaxf(m1, r1);
        float a0 = fexp(m0 - mn0), a1 = fexp(m1 - mn1);
        m0 = mn0; m1 = mn1;

        float s0 = 0.f, s1 = 0.f;
        #pragma unroll
        for (int nt = 0; nt < 8; nt++){
            s[nt][0] = fexp(s[nt][0] - mn0);
            s[nt][1] = fexp(s[nt][1] - mn0);
            s[nt][2] = fexp(s[nt][2] - mn1);
            s[nt][3] = fexp(s[nt][3] - mn1);
            s0 += s[nt][0] + s[nt][1];
            s1 += s[nt][2] + s[nt][3];
        }
        s0 += __shfl_xor_sync(~0u, s0, 1); s0 += __shfl_xor_sync(~0u, s0, 2);
        s1 += __shfl_xor_sync(~0u, s1, 1); s1 += __shfl_xor_sync(~0u, s1, 2);
        l0 = l0*a0 + s0; l1 = l1*a1 + s1;
        #pragma unroll
        for (int nt = 0; nt < 8; nt++){
            o[nt][0] *= a0; o[nt][1] *= a0; o[nt][2] *= a1; o[nt][3] *= a1;
        }

        // PV: O += Ph Vh + Ph Vl + Pl Vh
        #pragma unroll
        for (int ks = 0; ks < 4; ks++){
            uint32_t aPh[4], aPl[4];
            aPh[0] = packbf(s[2*ks][0],   s[2*ks][1]);
            aPh[1] = packbf(s[2*ks][2],   s[2*ks][3]);
            aPh[2] = packbf(s[2*ks+1][0], s[2*ks+1][1]);
            aPh[3] = packbf(s[2*ks+1][2], s[2*ks+1][3]);
            aPl[0] = packbf_lo(s[2*ks][0],   s[2*ks][1],   aPh[0]);
            aPl[1] = packbf_lo(s[2*ks][2],   s[2*ks][3],   aPh[1]);
            aPl[2] = packbf_lo(s[2*ks+1][0], s[2*ks+1][1], aPh[2]);
            aPl[3] = packbf_lo(s[2*ks+1][2], s[2*ks+1][3], aPh[3]);
            #pragma unroll
            for (int dp = 0; dp < 4; dp++){
                int rn = dp*16 + (gg >> 1)*8 + ii;
                int ck = ks*16 + (gg & 1)*8;
                uint32_t off = (uint32_t)(rn*FSP + ck)*2;
                uint32_t vh[4], vl[4];
                ldmx4(vh, st + 2*FTB + off);
                ldmx4(vl, st + 3*FTB + off);
                mma16816(o[2*dp],   aPh, vh);
                mma16816(o[2*dp],   aPh, vl);
                mma16816(o[2*dp],   aPl, vh);
                mma16816(o[2*dp+1], aPh, vh + 2);
                mma16816(o[2*dp+1], aPh, vl + 2);
                mma16816(o[2*dp+1], aPl, vh + 2);
            }
        }
        __syncthreads();
        if (t + 2 < 66){ load_stage(t + 2); CP_COMMIT(); }
    }

    // epilogue: normalize + split-store to g_ao
    float inv0 = 1.0f / l0, inv1 = 1.0f / l1;
    int g = lane >> 2;
    int row0 = q0 + wid*16 + g, row1 = row0 + 8;
    ll base0 = ((ll)(b*N) + row0)*INNER + h*64;
    ll base1 = ((ll)(b*N) + row1)*INNER + h*64;
    #pragma unroll
    for (int nt = 0; nt < 8; nt++){
        int c = nt*8 + tq*2;
        float v0 = o[nt][0]*inv0, v1 = o[nt][1]*inv0;
        float v2 = o[nt][2]*inv1, v3 = o[nt][3]*inv1;
        uint32_t h0 = packbf(v0, v1), l0p = packbf_lo(v0, v1, h0);
        uint32_t h1 = packbf(v2, v3), l1p = packbf_lo(v2, v3, h1);
        *(uint32_t*)(g_ao[0] + base0 + c) = h0;
        *(uint32_t*)(g_ao[1] + base0 + c) = l0p;
        *(uint32_t*)(g_ao[0] + base1 + c) = h1;
        *(uint32_t*)(g_ao[1] + base1 + c) = l1p;
    }
}

// ---------------- warp-mma split-bf16 GEMM ----------------
struct GemmArgs {
    const bf *Ah, *Al, *Bh, *Bl;
    int K, lda, ldb;
    ll sAb, sAh, sBb, sBh;
    float* Cf; const float* bias;
    bf *Ch, *Cl;
    ll sCb, sCh; int ldc, remap;
};

template<int NTILE>
__global__ __launch_bounds__(256, 1) void gemm_mma(GemmArgs g){
    constexpr int KC = 32, KPAD = 40;
    constexpr int WGM = (NTILE == 128) ? 2 : 4;
    constexpr int WGN = 8 / WGM;
    constexpr int WM = 128 / WGM;
    constexpr int WN = NTILE / WGN;
    constexpr int MT = WM / 16, NT = WN / 8;
    constexpr int ASZ = 128 * KPAD * 2;
    constexpr int BSZ = NTILE * KPAD * 2;
    constexpr int STAGE = 2*ASZ + 2*BSZ;
    constexpr int TOT = 1024 + NTILE*8;

    extern __shared__ __align__(16) char smem[];
    uint32_t sbase = sm_u32(smem);

    int tid = threadIdx.x, wid = tid >> 5, lane = tid & 31;
    int wm = wid % WGM, wn = wid / WGM;

    int zb = blockIdx.z >> 3, zh = blockIdx.z & 7;
    const bf* pAh = g.Ah + zb*g.sAb + zh*g.sAh + (ll)blockIdx.y*128*g.lda;
    const bf* pAl = g.Al + zb*g.sAb + zh*g.sAh + (ll)blockIdx.y*128*g.lda;
    const bf* pBh = g.Bh + zb*g.sBb + zh*g.sBh + (ll)blockIdx.x*NTILE*g.ldb;
    const bf* pBl = g.Bl + zb*g.sBb + zh*g.sBh + (ll)blockIdx.x*NTILE*g.ldb;

    float acc[MT][NT][4];
    #pragma unroll
    for (int i = 0; i < MT; i++)
        #pragma unroll
        for (int j = 0; j < NT; j++)
            #pragma unroll
            for (int e = 0; e < 4; e++) acc[i][j][e] = 0.f;

    int nch = g.K / KC;

    auto load_chunk = [&](int c){
        int s = c & 1, k0 = c * KC;
        uint32_t st = sbase + s*STAGE;
        #pragma unroll 2
        for (int u = tid; u < TOT; u += 256){
            const bf* src; uint32_t doff; int rel, ld;
            if (u < 512)              { rel = u;              src = pAh; doff = 0;         ld = g.lda; }
            else if (u < 1024)        { rel = u - 512;        src = pAl; doff = ASZ;       ld = g.lda; }
            else if (u < 1024+NTILE*4){ rel = u - 1024;       src = pBh; doff = 2*ASZ;     ld = g.ldb; }
            else                      { rel = u-1024-NTILE*4; src = pBl; doff = 2*ASZ+BSZ; ld = g.ldb; }
            int r = rel >> 2, sg = rel & 3;
            CP_ASYNC(st + doff + (uint32_t)(r*KPAD + sg*8)*2, src + (ll)r*ld + k0 + sg*8);
        }
        CP_COMMIT();
    };

    load_chunk(0);
    for (int c = 0; c < nch; c++){
        if (c + 1 < nch){ load_chunk(c + 1); CP_WAIT1(); }
        else            { CP_WAIT0(); }
        __syncthreads();

        uint32_t stg = sbase + (c & 1)*STAGE;
        #pragma unroll
        for (int ks = 0; ks < 2; ks++){
            int kb = ks * 16;
            uint32_t aH[MT][4], aL[MT][4];
            #pragma unroll
            for (int mt = 0; mt < MT; mt++){
                int row = wm*WM + mt*16 + (lane & 15);
                int col = kb + (lane >> 4)*8;
                uint32_t ad = stg + (uint32_t)(row*KPAD + col)*2;
                ldmx4(aH[mt], ad);
                ldmx4(aL[mt], ad + ASZ);
            }
            #pragma unroll
            for (int p = 0; p < NT/2; p++){
                int gg = lane >> 3, ii = lane & 7;
                int row = wn*WN + p*16 + (gg >> 1)*8 + ii;
                int col = kb + (gg & 1)*8;
                uint32_t bd = stg + 2*ASZ + (uint32_t)(row*KPAD + col)*2;
                uint32_t bH[4], bL[4];
                ldmx4(bH, bd);
                ldmx4(bL, bd + BSZ);
                #pragma unroll
                for (int mt = 0; mt < MT; mt++){
                    mma16816(acc[mt][2*p],   aH[mt], bH);
                    mma16816(acc[mt][2*p],   aH[mt], bL);
                    mma16816(acc[mt][2*p],   aL[mt], bH);
                    mma16816(acc[mt][2*p+1], aH[mt], bH + 2);
                    mma16816(acc[mt][2*p+1], aH[mt], bL + 2);
                    mma16816(acc[mt][2*p+1], aL[mt], bH + 2);
                }
            }
        }
        __syncthreads();
    }

    ll zoff = zb*g.sCb + zh*g.sCh;
    int ncb = blockIdx.x*NTILE + wn*WN;
    #pragma unroll
    for (int mt = 0; mt < MT; mt++){
        #pragma unroll
        for (int hf = 0; hf < 2; hf++){
            int row = blockIdx.y*128 + wm*WM + mt*16 + (lane >> 2) + hf*8;
            ll orow = (ll)(row >> 12)*g.remap + (row & 4095);
            ll basei = zoff + orow*(ll)g.ldc + ncb;
            #pragma unroll
            for (int nt = 0; nt < NT; nt++){
                int cl = nt*8 + (lane & 3)*2;
                float v0 = acc[mt][nt][hf*2], v1 = acc[mt][nt][hf*2+1];
                if (g.Cf){
                    if (g.bias){ v0 += g.bias[ncb + cl]; v1 += g.bias[ncb + cl + 1]; }
                    float2 f2; f2.x = v0; f2.y = v1;
                    *(float2*)(g.Cf + basei + cl) = f2;
                } else {
                    bf h0 = __float2bfloat16(v0), h1 = __float2bfloat16(v1);
                    __nv_bfloat162 hh, ll2;
                    hh.x = h0; hh.y = h1;
                    ll2.x = __float2bfloat16(v0 - __bfloat162float(h0));
                    ll2.y = __float2bfloat16(v1 - __bfloat162float(h1));
                    *(__nv_bfloat162*)(g.Ch + basei + cl) = hh;
                    *(__nv_bfloat162*)(g.Cl + basei + cl) = ll2;
                }
            }
        }
    }
}

// ---------------- launch ----------------
extern "C" void kernel_launch(void* const* d_in, const int* in_sizes, int n_in,
                              void* d_out, int out_size){
    const float* x    = (const float*)d_in[0];
    const float* ctx  = (const float*)d_in[1];
    const unsigned char* mask = (const unsigned char*)d_in[2];
    const float* Wq   = (const float*)d_in[3];
    const float* Wk   = (const float*)d_in[4];
    const float* Wv   = (const float*)d_in[5];
    const float* Wkbg = (const float*)d_in[6];
    const float* Wvbg = (const float*)d_in[7];
    const float* Wout = (const float*)d_in[8];
    const float* bout = (const float*)d_in[9];
    float* out = (float*)d_out;

    bf *xs, *cs, *wq, *wk, *wv, *wo, *q, *k, *v, *ao;
    cudaGetSymbolAddress((void**)&xs, g_xs);
    cudaGetSymbolAddress((void**)&cs, g_cs);
    cudaGetSymbolAddress((void**)&wq, g_wq);
    cudaGetSymbolAddress((void**)&wk, g_wk);
    cudaGetSymbolAddress((void**)&wv, g_wv);
    cudaGetSymbolAddress((void**)&wo, g_wo);
    cudaGetSymbolAddress((void**)&q,  g_q);
    cudaGetSymbolAddress((void**)&k,  g_k);
    cudaGetSymbolAddress((void**)&v,  g_v);
    cudaGetSymbolAddress((void**)&ao, g_ao);
    const size_t XSZ = (size_t)B*N*QD, QSZ = (size_t)B*N*INNER;
    const size_t KSZ = (size_t)B*NKP*INNER;
    const size_t WSZ = (size_t)QD*INNER;

    const int SM128 = 2*(2*128*40*2 + 2*128*40*2);
    cudaFuncSetAttribute(gemm_mma<128>, cudaFuncAttributeMaxDynamicSharedMemorySize, SM128);
    cudaFuncSetAttribute(flash_kernel,  cudaFuncAttributeMaxDynamicSharedMemorySize, FSMEM);

    mask_conv_kernel<<<1, 256>>>(mask);
    zero_pad_kernel<<<(B*(NKP-N-1)*INNER + 255)/256, 256>>>();
    pooled_kernel<<<(B*QD + 255)/256, 256>>>(x);
    pack_split<<<(int)((XSZ/4 + 255)/256), 256>>>((const float4*)x,   xs, xs + XSZ, (int)(XSZ/4));
    pack_split<<<(int)((XSZ/4 + 255)/256), 256>>>((const float4*)ctx, cs, cs + XSZ, (int)(XSZ/4));
    packT<<<dim3(INNER/32, QD/32),    dim3(32, 8)>>>(Wq,   wq, wq + WSZ, QD, INNER);
    packT<<<dim3(INNER/32, QD/32),    dim3(32, 8)>>>(Wk,   wk, wk + WSZ, CD, INNER);
    packT<<<dim3(INNER/32, QD/32),    dim3(32, 8)>>>(Wv,   wv, wv + WSZ, CD, INNER);
    packT<<<dim3(QD/32,    INNER/32), dim3(32, 8)>>>(Wout, wo, wo + WSZ, INNER, QD);
    bg_kernel<<<(B*INNER + 255)/256, 256>>>(Wkbg, Wvbg);

    GemmArgs a;
    // q = x @ Wq
    a = { xs, xs + XSZ, wq, wq + WSZ, QD, QD, QD, 0, 0, 0, 0,
          nullptr, nullptr, q, q + QSZ, 0, 0, INNER, 4096 };
    gemm_mma<128><<<dim3(INNER/128, (B*N)/128, 1), 256, SM128>>>(a);
    // k = ctx @ Wk (rows remapped to NKP stride)
    a = { cs, cs + XSZ, wk, wk + WSZ, CD, CD, CD, 0, 0, 0, 0,
          nullptr, nullptr, k, k + KSZ, 0, 0, INNER, NKP };
    gemm_mma<128><<<dim3(INNER/128, (B*N)/128, 1), 256, SM128>>>(a);
    // v = ctx @ Wv
    a = { cs, cs + XSZ, wv, wv + WSZ, CD, CD, CD, 0, 0, 0, 0,
          nullptr, nullptr, v, v + KSZ, 0, 0, INNER, NKP };
    gemm_mma<128><<<dim3(INNER/128, (B*N)/128, 1), 256, SM128>>>(a);
    // vT for PV B-operand
    vtrans_kernel<<<dim3(NKP/32, DH/32, B*H), dim3(32, 8)>>>();
    // fused attention
    flash_kernel<<<dim3(N/64, B*H), 128, FSMEM>>>();
    // out = ao @ Wout + b
    a = { ao, ao + QSZ, wo, wo + WSZ, INNER, INNER, INNER, 0, 0, 0, 0,
          out, bout, nullptr, nullptr, 0, 0, QD, 4096 };
    gemm_mma<128><<<dim3(QD/128, (B*N)/128, 1), 256, SM128>>>(a);
}

// round 6
// speedup vs baseline: 3.7601x; 1.5095x over previous
#include <cuda_runtime.h>
#include <cuda_bf16.h>
#include <cstdint>

#define B     2
#define N     4096
#define QD    1024
#define CD    1024
#define H     8
#define DH    64
#define INNER 512
#define NK    4097
#define NKP   4224
typedef long long ll;
typedef __nv_bfloat16 bf;

// ---------------- device scratch ----------------
__device__ __align__(16) bf g_xs[2][B*N*QD];
__device__ __align__(16) bf g_cs[2][B*N*CD];
__device__ __align__(16) bf g_wq[2][QD*INNER];
__device__ __align__(16) bf g_wk[2][CD*INNER];
__device__ __align__(16) bf g_wv[2][CD*INNER];
__device__ __align__(16) bf g_wo[2][INNER*QD];
__device__ __align__(16) bf g_q [2][B*N*INNER];
__device__ __align__(16) bf g_k [2][B*NKP*INNER];    // full (orig key order)
__device__ __align__(16) bf g_v [2][B*NKP*INNER];
__device__ __align__(16) bf g_kd[2][B*NKP*INNER];    // dense (compacted keys)
__device__ __align__(16) bf g_vt[2][B*H*DH*NKP];     // dense, transposed
__device__ __align__(16) bf g_ao[2][B*N*INNER];
__device__ float g_ppart[16][B*QD];
__device__ float g_pooled[B*QD];
__device__ int g_gidx[B][NKP];
__device__ int g_nvalid[B];

// ---------------- helpers ----------------
__device__ __forceinline__ uint32_t sm_u32(const void* p){
    uint32_t a;
    asm("{ .reg .u64 t; cvta.to.shared.u64 t, %1; cvt.u32.u64 %0, t; }" : "=r"(a) : "l"(p));
    return a;
}
__device__ __forceinline__ void ldmx4(uint32_t* r, uint32_t addr){
    asm volatile("ldmatrix.sync.aligned.m8n8.x4.shared.b16 {%0,%1,%2,%3}, [%4];"
        : "=r"(r[0]), "=r"(r[1]), "=r"(r[2]), "=r"(r[3]) : "r"(addr));
}
__device__ __forceinline__ void mma16816(float* d, const uint32_t* a, const uint32_t* b){
    asm volatile("mma.sync.aligned.m16n8k16.row.col.f32.bf16.bf16.f32 "
        "{%0,%1,%2,%3}, {%4,%5,%6,%7}, {%8,%9}, {%0,%1,%2,%3};"
        : "+f"(d[0]), "+f"(d[1]), "+f"(d[2]), "+f"(d[3])
        : "r"(a[0]), "r"(a[1]), "r"(a[2]), "r"(a[3]), "r"(b[0]), "r"(b[1]));
}
#define CP_ASYNC(dst, src) \
    asm volatile("cp.async.cg.shared.global [%0], [%1], 16;" :: "r"(dst), "l"(src))
#define CP_COMMIT() asm volatile("cp.async.commit_group;" ::: "memory")
#define CP_WAIT1()  asm volatile("cp.async.wait_group 1;" ::: "memory")
#define CP_WAIT0()  asm volatile("cp.async.wait_group 0;" ::: "memory")

__device__ __forceinline__ uint32_t packbf(float a, float b){
    __nv_bfloat162 t; t.x = __float2bfloat16(a); t.y = __float2bfloat16(b);
    return *(uint32_t*)&t;
}
__device__ __forceinline__ uint32_t packbf_lo(float a, float b, uint32_t hi){
    __nv_bfloat162 h = *(__nv_bfloat162*)&hi;
    return packbf(a - __bfloat162float(h.x), b - __bfloat162float(h.y));
}
// fast exp on FMA pipe (finite args; very negative -> ~0)
__device__ __forceinline__ float fexp(float x){
    float t = fmaxf(x * 1.4426950409f, -120.f);
    float r = rintf(t);
    float f = t - r;
    float p = 1.33336e-3f;
    p = fmaf(p, f, 9.61812e-3f);
    p = fmaf(p, f, 5.55041e-2f);
    p = fmaf(p, f, 2.4022651e-1f);
    p = fmaf(p, f, 6.9314718e-1f);
    p = fmaf(p, f, 1.0f);
    return p * __int_as_float(((int)r + 127) << 23);
}

// ---------------- mask scan: format detect + per-batch compaction ----------------
__global__ void scan_kernel(const unsigned char* __restrict__ m){
    __shared__ int anynz;
    __shared__ int sc[256];
    int tid = threadIdx.x, b = blockIdx.x;
    if (tid == 0) anynz = 0;
    __syncthreads();
    int loc = 0;
    for (int i = tid; i < 8192; i += 256)
        if ((i & 3) && m[i]) loc = 1;
    if (loc) atomicOr(&anynz, 1);
    __syncthreads();
    bool u8 = (anynz != 0);
    const int* mi = (const int*)m;

    // per-thread chunk of 17 mask entries
    int base = tid * 17, c = 0;
    unsigned int bits = 0;
    #pragma unroll
    for (int e = 0; e < 17; e++){
        int w = base + e;
        int on = 0;
        if (w < NK) on = u8 ? (m[b*NK + w] != 0) : (mi[b*NK + w] != 0);
        bits |= (unsigned)on << e;
        c += on;
    }
    sc[tid] = c;
    __syncthreads();
    // Hillis-Steele inclusive scan
    for (int off = 1; off < 256; off <<= 1){
        int v = (tid >= off) ? sc[tid - off] : 0;
        __syncthreads();
        sc[tid] += v;
        __syncthreads();
    }
    int pos = sc[tid] - c;
    #pragma unroll
    for (int e = 0; e < 17; e++)
        if ((bits >> e) & 1) g_gidx[b][pos++] = base + e;
    if (tid == 255) g_nvalid[b] = sc[255];
}

// ---------------- pooled mean (two-phase, deterministic) ----------------
__global__ void pooled_p1(const float* __restrict__ x){
    int id = blockIdx.x*256 + threadIdx.x;          // (b,d)
    int chunk = blockIdx.y;                          // 16 chunks of 256 rows
    int b = id / QD, d = id % QD;
    const float* p = x + (size_t)b*N*QD + (size_t)chunk*256*QD + d;
    float s = 0.f;
    #pragma unroll 8
    for (int n = 0; n < 256; n++) s += p[(size_t)n*QD];
    g_ppart[chunk][id] = s;
}
__global__ void pooled_p2(){
    int id = blockIdx.x*256 + threadIdx.x;
    if (id >= B*QD) return;
    float s = 0.f;
    #pragma unroll
    for (int c = 0; c < 16; c++) s += g_ppart[c][id];
    g_pooled[id] = s * (1.0f/N);
}

__global__ void bg_kernel(const float* __restrict__ Wkbg, const float* __restrict__ Wvbg){
    int id = blockIdx.x*256 + threadIdx.x;
    if (id >= B*INNER) return;
    int b = id / INNER, o = id % INNER;
    float sk = 0.f, sv = 0.f;
    for (int k = 0; k < QD; k++){
        float pv = g_pooled[b*QD + k];
        sk += pv * Wkbg[(size_t)k*INNER + o];
        sv += pv * Wvbg[(size_t)k*INNER + o];
    }
    size_t base = (size_t)(b*NKP + N)*INNER + o;
    bf h;
    h = __float2bfloat16(sk); g_k[0][base] = h; g_k[1][base] = __float2bfloat16(sk - __bfloat162float(h));
    h = __float2bfloat16(sv); g_v[0][base] = h; g_v[1][base] = __float2bfloat16(sv - __bfloat162float(h));
}

__global__ void pack_split(const float4* __restrict__ src, bf* __restrict__ hi, bf* __restrict__ lo, int n4){
    int i = blockIdx.x*256 + threadIdx.x;
    if (i >= n4) return;
    float4 v = src[i];
    float vv[4] = {v.x, v.y, v.z, v.w};
    __nv_bfloat162 h2[2], l2[2];
    #pragma unroll
    for (int j = 0; j < 4; j++){
        bf h = __float2bfloat16(vv[j]);
        bf l = __float2bfloat16(vv[j] - __bfloat162float(h));
        ((bf*)h2)[j] = h; ((bf*)l2)[j] = l;
    }
    ((__nv_bfloat162*)hi)[i*2]   = h2[0]; ((__nv_bfloat162*)hi)[i*2+1] = h2[1];
    ((__nv_bfloat162*)lo)[i*2]   = l2[0]; ((__nv_bfloat162*)lo)[i*2+1] = l2[1];
}

__global__ void packT(const float* __restrict__ src, bf* __restrict__ hi, bf* __restrict__ lo, int R, int C){
    __shared__ float t[32][33];
    int c0 = blockIdx.x*32, r0 = blockIdx.y*32;
    for (int i = threadIdx.y; i < 32; i += 8)
        t[i][threadIdx.x] = src[(size_t)(r0+i)*C + c0 + threadIdx.x];
    __syncthreads();
    for (int i = threadIdx.y; i < 32; i += 8){
        float v = t[threadIdx.x][i];
        size_t o = (size_t)(c0+i)*R + r0 + threadIdx.x;
        bf h = __float2bfloat16(v);
        hi[o] = h; lo[o] = __float2bfloat16(v - __bfloat162float(h));
    }
}

// gather k rows into dense order (i < nvalid)
__global__ void gather_k(){
    int id = blockIdx.x*256 + threadIdx.x;           // B*NKP*64 uint4 slots
    int b = id / (NKP*64);
    int rem = id - b*NKP*64;
    int i = rem >> 6, seg = rem & 63;
    if (i >= g_nvalid[b]) return;
    int src = g_gidx[b][i];
    size_t so = ((size_t)(b*NKP + src))*INNER + seg*8;
    size_t dofs = ((size_t)(b*NKP + i))*INNER + seg*8;
    *(uint4*)(g_kd[0] + dofs) = *(const uint4*)(g_k[0] + so);
    *(uint4*)(g_kd[1] + dofs) = *(const uint4*)(g_k[1] + so);
}

// gather + transpose v into dense g_vt; zero tail (>= nvalid)
__global__ void vtrans_kernel(){
    __shared__ bf t[2][32][33];
    int z = blockIdx.z, b = z >> 3, h = z & 7;
    int j0 = blockIdx.x*32, d0 = blockIdx.y*32;
    int tx = threadIdx.x, ty = threadIdx.y;
    int nv = g_nvalid[b];
    #pragma unroll
    for (int s = 0; s < 2; s++)
        for (int i = ty; i < 32; i += 8){
            int jd = j0 + i;
            bf val = __float2bfloat16(0.f);
            if (jd < nv){
                int src = g_gidx[b][jd];
                val = g_v[s][(size_t)(b*NKP + src)*INNER + h*64 + d0 + tx];
            }
            t[s][i][tx] = val;
        }
    __syncthreads();
    #pragma unroll
    for (int s = 0; s < 2; s++)
        for (int i = ty; i < 32; i += 8)
            g_vt[s][((size_t)z*DH + d0 + i)*NKP + j0 + tx] = t[s][tx][i];
}

// ---------------- fused flash attention over dense keys ----------------
#define FSP 72
#define FTB (64*FSP*2)
#define FSTG (4*FTB)
#define FSMEM (2*FTB + 2*FSTG + 128)

__global__ __launch_bounds__(128, 2) void flash_kernel(){
    extern __shared__ __align__(16) char fsm[];
    const int tid = threadIdx.x, wid = tid >> 5, lane = tid & 31;
    const int z = blockIdx.y, b = z >> 3, h = z & 7;
    const int q0 = blockIdx.x*64;
    uint32_t sb = sm_u32(fsm);
    const uint32_t oQ = 0, oS = 2*FTB;

    const int nv = g_nvalid[b];
    const int ntiles = (nv + 63) >> 6;

    const bf* Qg[2] = { g_q[0] + ((size_t)(b*N + q0))*INNER + h*64,
                        g_q[1] + ((size_t)(b*N + q0))*INNER + h*64 };
    const bf* Kg[2] = { g_kd[0] + (size_t)b*NKP*INNER + h*64,
                        g_kd[1] + (size_t)b*NKP*INNER + h*64 };
    const bf* Vg[2] = { g_vt[0] + (size_t)z*DH*NKP,
                        g_vt[1] + (size_t)z*DH*NKP };

    auto load_stage = [&](int t){
        int j0 = t*64;
        uint32_t st = sb + oS + (t & 1)*FSTG;
        #pragma unroll 4
        for (int u = tid; u < 2048; u += 128){
            int tile = u >> 9, r = (u >> 3) & 63, sg = u & 7;
            const bf* src;
            if (tile == 0)      src = Kg[0] + (size_t)(j0 + r)*INNER + sg*8;
            else if (tile == 1) src = Kg[1] + (size_t)(j0 + r)*INNER + sg*8;
            else if (tile == 2) src = Vg[0] + (size_t)r*NKP + j0 + sg*8;
            else                src = Vg[1] + (size_t)r*NKP + j0 + sg*8;
            CP_ASYNC(st + tile*FTB + (uint32_t)(r*FSP + sg*8)*2, src);
        }
    };

    #pragma unroll 4
    for (int u = tid; u < 1024; u += 128){
        int half = u >> 9, r = (u >> 3) & 63, sg = u & 7;
        CP_ASYNC(sb + oQ + half*FTB + (uint32_t)(r*FSP + sg*8)*2,
                 Qg[half] + (size_t)r*INNER + sg*8);
    }
    if (ntiles > 0) load_stage(0);
    CP_COMMIT();
    if (ntiles > 1) load_stage(1);
    CP_COMMIT();

    uint32_t aQh[4][4], aQl[4][4];
    float m0 = -1e30f, m1 = -1e30f, l0 = 0.f, l1 = 0.f;
    float o[8][4];
    #pragma unroll
    for (int i = 0; i < 8; i++){ o[i][0]=0.f; o[i][1]=0.f; o[i][2]=0.f; o[i][3]=0.f; }

    const int gg = lane >> 3, ii = lane & 7, tq = lane & 3;

    for (int t = 0; t < ntiles; t++){
        if (t + 2 < ntiles) CP_WAIT1(); else CP_WAIT0();
        __syncthreads();

        if (t == 0){
            int row = wid*16 + (lane & 15);
            int col = (lane >> 4)*8;
            #pragma unroll
            for (int ks = 0; ks < 4; ks++){
                uint32_t ad = sb + oQ + (uint32_t)(row*FSP + ks*16 + col)*2;
                ldmx4(aQh[ks], ad);
                ldmx4(aQl[ks], ad + FTB);
            }
        }

        uint32_t st = sb + oS + (t & 1)*FSTG;

        float s[8][4];
        #pragma unroll
        for (int i = 0; i < 8; i++){ s[i][0]=0.f; s[i][1]=0.f; s[i][2]=0.f; s[i][3]=0.f; }
        #pragma unroll
        for (int ks = 0; ks < 4; ks++){
            #pragma unroll
            for (int p = 0; p < 4; p++){
                int rn = p*16 + (gg >> 1)*8 + ii;
                int ck = ks*16 + (gg & 1)*8;
                uint32_t off = (uint32_t)(rn*FSP + ck)*2;
                uint32_t bh[4], bl[4];
                ldmx4(bh, st + off);
                ldmx4(bl, st + FTB + off);
                mma16816(s[2*p],   aQh[ks], bh);
                mma16816(s[2*p],   aQh[ks], bl);
                mma16816(s[2*p],   aQl[ks], bh);
                mma16816(s[2*p+1], aQh[ks], bh + 2);
                mma16816(s[2*p+1], aQh[ks], bl + 2);
                mma16816(s[2*p+1], aQl[ks], bh + 2);
            }
        }

        // dense-index mask + scale
        int jb = t*64;
        #pragma unroll
        for (int nt = 0; nt < 8; nt++){
            int c0 = jb + nt*8 + tq*2;
            bool k0 = c0 < nv, k1 = (c0 + 1) < nv;
            s[nt][0] = k0 ? s[nt][0]*0.125f : -1e30f;
            s[nt][1] = k1 ? s[nt][1]*0.125f : -1e30f;
            s[nt][2] = k0 ? s[nt][2]*0.125f : -1e30f;
            s[nt][3] = k1 ? s[nt][3]*0.125f : -1e30f;
        }

        float r0 = -1e30f, r1 = -1e30f;
        #pragma unroll
        for (int nt = 0; nt < 8; nt++){
            r0 = fmaxf(r0, fmaxf(s[nt][0], s[nt][1]));
            r1 = fmaxf(r1, fmaxf(s[nt][2], s[nt][3]));
        }
        r0 = fmaxf(r0, __shfl_xor_sync(~0u, r0, 1));
        r0 = fmaxf(r0, __shfl_xor_sync(~0u, r0, 2));
        r1 = fmaxf(r1, __shfl_xor_sync(~0u, r1, 1));
        r1 = fmaxf(r1, __shfl_xor_sync(~0u, r1, 2));
        float mn0 = fmaxf(m0, r0), mn1 = fmaxf(m1, r1);
        float a0 = fexp(m0 - mn0), a1 = fexp(m1 - mn1);
        m0 = mn0; m1 = mn1;

        float s0 = 0.f, s1 = 0.f;
        #pragma unroll
        for (int nt = 0; nt < 8; nt++){
            s[nt][0] = fexp(s[nt][0] - mn0);
            s[nt][1] = fexp(s[nt][1] - mn0);
            s[nt][2] = fexp(s[nt][2] - mn1);
            s[nt][3] = fexp(s[nt][3] - mn1);
            s0 += s[nt][0] + s[nt][1];
            s1 += s[nt][2] + s[nt][3];
        }
        s0 += __shfl_xor_sync(~0u, s0, 1); s0 += __shfl_xor_sync(~0u, s0, 2);
        s1 += __shfl_xor_sync(~0u, s1, 1); s1 += __shfl_xor_sync(~0u, s1, 2);
        l0 = l0*a0 + s0; l1 = l1*a1 + s1;
        #pragma unroll
        for (int nt = 0; nt < 8; nt++){
            o[nt][0] *= a0; o[nt][1] *= a0; o[nt][2] *= a1; o[nt][3] *= a1;
        }

        #pragma unroll
        for (int ks = 0; ks < 4; ks++){
            uint32_t aPh[4], aPl[4];
            aPh[0] = packbf(s[2*ks][0],   s[2*ks][1]);
            aPh[1] = packbf(s[2*ks][2],   s[2*ks][3]);
            aPh[2] = packbf(s[2*ks+1][0], s[2*ks+1][1]);
            aPh[3] = packbf(s[2*ks+1][2], s[2*ks+1][3]);
            aPl[0] = packbf_lo(s[2*ks][0],   s[2*ks][1],   aPh[0]);
            aPl[1] = packbf_lo(s[2*ks][2],   s[2*ks][3],   aPh[1]);
            aPl[2] = packbf_lo(s[2*ks+1][0], s[2*ks+1][1], aPh[2]);
            aPl[3] = packbf_lo(s[2*ks+1][2], s[2*ks+1][3], aPh[3]);
            #pragma unroll
            for (int dp = 0; dp < 4; dp++){
                int rn = dp*16 + (gg >> 1)*8 + ii;
                int ck = ks*16 + (gg & 1)*8;
                uint32_t off = (uint32_t)(rn*FSP + ck)*2;
                uint32_t vh[4], vl[4];
                ldmx4(vh, st + 2*FTB + off);
                ldmx4(vl, st + 3*FTB + off);
                mma16816(o[2*dp],   aPh, vh);
                mma16816(o[2*dp],   aPh, vl);
                mma16816(o[2*dp],   aPl, vh);
                mma16816(o[2*dp+1], aPh, vh + 2);
                mma16816(o[2*dp+1], aPh, vl + 2);
                mma16816(o[2*dp+1], aPl, vh + 2);
            }
        }
        __syncthreads();
        if (t + 2 < ntiles){ load_stage(t + 2); CP_COMMIT(); }
    }

    float inv0 = 1.0f / l0, inv1 = 1.0f / l1;
    int g = lane >> 2;
    int row0 = q0 + wid*16 + g, row1 = row0 + 8;
    ll base0 = ((ll)(b*N) + row0)*INNER + h*64;
    ll base1 = ((ll)(b*N) + row1)*INNER + h*64;
    #pragma unroll
    for (int nt = 0; nt < 8; nt++){
        int c = nt*8 + tq*2;
        float v0 = o[nt][0]*inv0, v1 = o[nt][1]*inv0;
        float v2 = o[nt][2]*inv1, v3 = o[nt][3]*inv1;
        uint32_t h0 = packbf(v0, v1), l0p = packbf_lo(v0, v1, h0);
        uint32_t h1 = packbf(v2, v3), l1p = packbf_lo(v2, v3, h1);
        *(uint32_t*)(g_ao[0] + base0 + c) = h0;
        *(uint32_t*)(g_ao[1] + base0 + c) = l0p;
        *(uint32_t*)(g_ao[0] + base1 + c) = h1;
        *(uint32_t*)(g_ao[1] + base1 + c) = l1p;
    }
}

// ---------------- warp-mma split-bf16 GEMM ----------------
struct GemmArgs {
    const bf *Ah, *Al, *Bh, *Bl;
    int K, lda, ldb;
    ll sAb, sAh, sBb, sBh;
    float* Cf; const float* bias;
    bf *Ch, *Cl;
    ll sCb, sCh; int ldc, remap;
};

template<int NTILE>
__global__ __launch_bounds__(256, 1) void gemm_mma(GemmArgs g){
    constexpr int KC = 32, KPAD = 40;
    constexpr int WGM = (NTILE == 128) ? 2 : 4;
    constexpr int WGN = 8 / WGM;
    constexpr int WM = 128 / WGM;
    constexpr int WN = NTILE / WGN;
    constexpr int MT = WM / 16, NT = WN / 8;
    constexpr int ASZ = 128 * KPAD * 2;
    constexpr int BSZ = NTILE * KPAD * 2;
    constexpr int STAGE = 2*ASZ + 2*BSZ;
    constexpr int TOT = 1024 + NTILE*8;

    extern __shared__ __align__(16) char smem[];
    uint32_t sbase = sm_u32(smem);

    int tid = threadIdx.x, wid = tid >> 5, lane = tid & 31;
    int wm = wid % WGM, wn = wid / WGM;

    int zb = blockIdx.z >> 3, zh = blockIdx.z & 7;
    const bf* pAh = g.Ah + zb*g.sAb + zh*g.sAh + (ll)blockIdx.y*128*g.lda;
    const bf* pAl = g.Al + zb*g.sAb + zh*g.sAh + (ll)blockIdx.y*128*g.lda;
    const bf* pBh = g.Bh + zb*g.sBb + zh*g.sBh + (ll)blockIdx.x*NTILE*g.ldb;
    const bf* pBl = g.Bl + zb*g.sBb + zh*g.sBh + (ll)blockIdx.x*NTILE*g.ldb;

    float acc[MT][NT][4];
    #pragma unroll
    for (int i = 0; i < MT; i++)
        #pragma unroll
        for (int j = 0; j < NT; j++)
            #pragma unroll
            for (int e = 0; e < 4; e++) acc[i][j][e] = 0.f;

    int nch = g.K / KC;

    auto load_chunk = [&](int c){
        int s = c & 1, k0 = c * KC;
        uint32_t st = sbase + s*STAGE;
        #pragma unroll 2
        for (int u = tid; u < TOT; u += 256){
            const bf* src; uint32_t doff; int rel, ld;
            if (u < 512)              { rel = u;              src = pAh; doff = 0;         ld = g.lda; }
            else if (u < 1024)        { rel = u - 512;        src = pAl; doff = ASZ;       ld = g.lda; }
            else if (u < 1024+NTILE*4){ rel = u - 1024;       src = pBh; doff = 2*ASZ;     ld = g.ldb; }
            else                      { rel = u-1024-NTILE*4; src = pBl; doff = 2*ASZ+BSZ; ld = g.ldb; }
            int r = rel >> 2, sg = rel & 3;
            CP_ASYNC(st + doff + (uint32_t)(r*KPAD + sg*8)*2, src + (ll)r*ld + k0 + sg*8);
        }
        CP_COMMIT();
    };

    load_chunk(0);
    for (int c = 0; c < nch; c++){
        if (c + 1 < nch){ load_chunk(c + 1); CP_WAIT1(); }
        else            { CP_WAIT0(); }
        __syncthreads();

        uint32_t stg = sbase + (c & 1)*STAGE;
        #pragma unroll
        for (int ks = 0; ks < 2; ks++){
            int kb = ks * 16;
            uint32_t aH[MT][4], aL[MT][4];
            #pragma unroll
            for (int mt = 0; mt < MT; mt++){
                int row = wm*WM + mt*16 + (lane & 15);
                int col = kb + (lane >> 4)*8;
                uint32_t ad = stg + (uint32_t)(row*KPAD + col)*2;
                ldmx4(aH[mt], ad);
                ldmx4(aL[mt], ad + ASZ);
            }
            #pragma unroll
            for (int p = 0; p < NT/2; p++){
                int gg = lane >> 3, ii = lane & 7;
                int row = wn*WN + p*16 + (gg >> 1)*8 + ii;
                int col = kb + (gg & 1)*8;
                uint32_t bd = stg + 2*ASZ + (uint32_t)(row*KPAD + col)*2;
                uint32_t bH[4], bL[4];
                ldmx4(bH, bd);
                ldmx4(bL, bd + BSZ);
                #pragma unroll
                for (int mt = 0; mt < MT; mt++){
                    mma16816(acc[mt][2*p],   aH[mt], bH);
                    mma16816(acc[mt][2*p],   aH[mt], bL);
                    mma16816(acc[mt][2*p],   aL[mt], bH);
                    mma16816(acc[mt][2*p+1], aH[mt], bH + 2);
                    mma16816(acc[mt][2*p+1], aH[mt], bL + 2);
                    mma16816(acc[mt][2*p+1], aL[mt], bH + 2);
                }
            }
        }
        __syncthreads();
    }

    ll zoff = zb*g.sCb + zh*g.sCh;
    int ncb = blockIdx.x*NTILE + wn*WN;
    #pragma unroll
    for (int mt = 0; mt < MT; mt++){
        #pragma unroll
        for (int hf = 0; hf < 2; hf++){
            int row = blockIdx.y*128 + wm*WM + mt*16 + (lane >> 2) + hf*8;
            ll orow = (ll)(row >> 12)*g.remap + (row & 4095);
            ll basei = zoff + orow*(ll)g.ldc + ncb;
            #pragma unroll
            for (int nt = 0; nt < NT; nt++){
                int cl = nt*8 + (lane & 3)*2;
                float v0 = acc[mt][nt][hf*2], v1 = acc[mt][nt][hf*2+1];
                if (g.Cf){
                    if (g.bias){ v0 += g.bias[ncb + cl]; v1 += g.bias[ncb + cl + 1]; }
                    float2 f2; f2.x = v0; f2.y = v1;
                    *(float2*)(g.Cf + basei + cl) = f2;
                } else {
                    bf h0 = __float2bfloat16(v0), h1 = __float2bfloat16(v1);
                    __nv_bfloat162 hh, ll2;
                    hh.x = h0; hh.y = h1;
                    ll2.x = __float2bfloat16(v0 - __bfloat162float(h0));
                    ll2.y = __float2bfloat16(v1 - __bfloat162float(h1));
                    *(__nv_bfloat162*)(g.Ch + basei + cl) = hh;
                    *(__nv_bfloat162*)(g.Cl + basei + cl) = ll2;
                }
            }
        }
    }
}

// ---------------- launch ----------------
extern "C" void kernel_launch(void* const* d_in, const int* in_sizes, int n_in,
                              void* d_out, int out_size){
    const float* x    = (const float*)d_in[0];
    const float* ctx  = (const float*)d_in[1];
    const unsigned char* mask = (const unsigned char*)d_in[2];
    const float* Wq   = (const float*)d_in[3];
    const float* Wk   = (const float*)d_in[4];
    const float* Wv   = (const float*)d_in[5];
    const float* Wkbg = (const float*)d_in[6];
    const float* Wvbg = (const float*)d_in[7];
    const float* Wout = (const float*)d_in[8];
    const float* bout = (const float*)d_in[9];
    float* out = (float*)d_out;

    bf *xs, *cs, *wq, *wk, *wv, *wo, *q, *k, *v, *ao;
    cudaGetSymbolAddress((void**)&xs, g_xs);
    cudaGetSymbolAddress((void**)&cs, g_cs);
    cudaGetSymbolAddress((void**)&wq, g_wq);
    cudaGetSymbolAddress((void**)&wk, g_wk);
    cudaGetSymbolAddress((void**)&wv, g_wv);
    cudaGetSymbolAddress((void**)&wo, g_wo);
    cudaGetSymbolAddress((void**)&q,  g_q);
    cudaGetSymbolAddress((void**)&k,  g_k);
    cudaGetSymbolAddress((void**)&v,  g_v);
    cudaGetSymbolAddress((void**)&ao, g_ao);
    const size_t XSZ = (size_t)B*N*QD, QSZ = (size_t)B*N*INNER;
    const size_t KSZ = (size_t)B*NKP*INNER;
    const size_t WSZ = (size_t)QD*INNER;

    const int SM128 = 2*(2*128*40*2 + 2*128*40*2);
    cudaFuncSetAttribute(gemm_mma<128>, cudaFuncAttributeMaxDynamicSharedMemorySize, SM128);
    cudaFuncSetAttribute(flash_kernel,  cudaFuncAttributeMaxDynamicSharedMemorySize, FSMEM);

    scan_kernel<<<B, 256>>>(mask);
    pooled_p1<<<dim3(B*QD/256, 16), 256>>>(x);
    pooled_p2<<<(B*QD + 255)/256, 256>>>();
    pack_split<<<(int)((XSZ/4 + 255)/256), 256>>>((const float4*)x,   xs, xs + XSZ, (int)(XSZ/4));
    pack_split<<<(int)((XSZ/4 + 255)/256), 256>>>((const float4*)ctx, cs, cs + XSZ, (int)(XSZ/4));
    packT<<<dim3(INNER/32, QD/32),    dim3(32, 8)>>>(Wq,   wq, wq + WSZ, QD, INNER);
    packT<<<dim3(INNER/32, QD/32),    dim3(32, 8)>>>(Wk,   wk, wk + WSZ, CD, INNER);
    packT<<<dim3(INNER/32, QD/32),    dim3(32, 8)>>>(Wv,   wv, wv + WSZ, CD, INNER);
    packT<<<dim3(QD/32,    INNER/32), dim3(32, 8)>>>(Wout, wo, wo + WSZ, INNER, QD);
    bg_kernel<<<(B*INNER + 255)/256, 256>>>(Wkbg, Wvbg);

    GemmArgs a;
    // q = x @ Wq
    a = { xs, xs + XSZ, wq, wq + WSZ, QD, QD, QD, 0, 0, 0, 0,
          nullptr, nullptr, q, q + QSZ, 0, 0, INNER, 4096 };
    gemm_mma<128><<<dim3(INNER/128, (B*N)/128, 1), 256, SM128>>>(a);
    // k = ctx @ Wk (rows remapped to NKP stride)
    a = { cs, cs + XSZ, wk, wk + WSZ, CD, CD, CD, 0, 0, 0, 0,
          nullptr, nullptr, k, k + KSZ, 0, 0, INNER, NKP };
    gemm_mma<128><<<dim3(INNER/128, (B*N)/128, 1), 256, SM128>>>(a);
    // v = ctx @ Wv
    a = { cs, cs + XSZ, wv, wv + WSZ, CD, CD, CD, 0, 0, 0, 0,
          nullptr, nullptr, v, v + KSZ, 0, 0, INNER, NKP };
    gemm_mma<128><<<dim3(INNER/128, (B*N)/128, 1), 256, SM128>>>(a);
    // compaction (after k/v GEMMs + bg)
    gather_k<<<(B*NKP*64 + 255)/256, 256>>>();
    vtrans_kernel<<<dim3(NKP/32, DH/32, B*H), dim3(32, 8)>>>();
    // fused attention over dense keys
    flash_kernel<<<dim3(N/64, B*H), 128, FSMEM>>>();
    // out = ao @ Wout + b
    a = { ao, ao + QSZ, wo, wo + WSZ, INNER, INNER, INNER, 0, 0, 0, 0,
          out, bout, nullptr, nullptr, 0, 0, QD, 4096 };
    gemm_mma<128><<<dim3(QD/128, (B*N)/128, 1), 256, SM128>>>(a);
}

// round 7
// speedup vs baseline: 4.0586x; 1.0794x over previous
#include <cuda_runtime.h>
#include <cuda_bf16.h>
#include <cstdint>

#define B     2
#define N     4096
#define QD    1024
#define CD    1024
#define H     8
#define DH    64
#define INNER 512
#define NK    4097
#define NKP   4224
typedef long long ll;
typedef __nv_bfloat16 bf;

// ---------------- device scratch ----------------
__device__ __align__(16) bf g_xs[2][B*N*QD];
__device__ __align__(16) bf g_cs[2][B*N*CD];
__device__ __align__(16) bf g_wq[2][QD*INNER];
__device__ __align__(16) bf g_wk[2][CD*INNER];
__device__ __align__(16) bf g_wv[2][CD*INNER];
__device__ __align__(16) bf g_wo[2][INNER*QD];
__device__ __align__(16) bf g_q [2][B*N*INNER];
__device__ __align__(16) bf g_v [2][B*NKP*INNER];    // full (orig key order)
__device__ __align__(16) bf g_kd[2][B*NKP*INNER];    // dense (compacted keys)
__device__ __align__(16) bf g_vt[2][B*H*DH*NKP];     // dense, transposed
__device__ __align__(16) bf g_ao[2][B*N*INNER];
__device__ float g_ppart[16][B*QD];
__device__ float g_pooled[B*QD];
__device__ int g_gidx[B][NKP];    // dense -> orig
__device__ int g_scat[B*NKP];     // orig -> dense (or -1)
__device__ int g_nvalid[B];

// ---------------- helpers ----------------
__device__ __forceinline__ uint32_t sm_u32(const void* p){
    uint32_t a;
    asm("{ .reg .u64 t; cvta.to.shared.u64 t, %1; cvt.u32.u64 %0, t; }" : "=r"(a) : "l"(p));
    return a;
}
__device__ __forceinline__ void ldmx4(uint32_t* r, uint32_t addr){
    asm volatile("ldmatrix.sync.aligned.m8n8.x4.shared.b16 {%0,%1,%2,%3}, [%4];"
        : "=r"(r[0]), "=r"(r[1]), "=r"(r[2]), "=r"(r[3]) : "r"(addr));
}
__device__ __forceinline__ void mma16816(float* d, const uint32_t* a, const uint32_t* b){
    asm volatile("mma.sync.aligned.m16n8k16.row.col.f32.bf16.bf16.f32 "
        "{%0,%1,%2,%3}, {%4,%5,%6,%7}, {%8,%9}, {%0,%1,%2,%3};"
        : "+f"(d[0]), "+f"(d[1]), "+f"(d[2]), "+f"(d[3])
        : "r"(a[0]), "r"(a[1]), "r"(a[2]), "r"(a[3]), "r"(b[0]), "r"(b[1]));
}
#define CP_ASYNC(dst, src) \
    asm volatile("cp.async.cg.shared.global [%0], [%1], 16;" :: "r"(dst), "l"(src))
#define CP_COMMIT() asm volatile("cp.async.commit_group;" ::: "memory")
#define CP_WAIT1()  asm volatile("cp.async.wait_group 1;" ::: "memory")
#define CP_WAIT0()  asm volatile("cp.async.wait_group 0;" ::: "memory")

// bf16x2 pack: lo = a, hi = b (single cvt instruction)
__device__ __forceinline__ uint32_t packbf(float a, float b){
    uint32_t r;
    asm("cvt.rn.bf16x2.f32 %0, %1, %2;" : "=r"(r) : "f"(b), "f"(a));
    return r;
}
__device__ __forceinline__ uint32_t packbf_lo(float a, float b, uint32_t hi){
    float hx = __uint_as_float((hi & 0xFFFFu) << 16);
    float hy = __uint_as_float(hi & 0xFFFF0000u);
    return packbf(a - hx, b - hy);
}
// fast exp on FMA pipe (clamps very negative to ~0; safe to x ~ +80)
__device__ __forceinline__ float fexp(float x){
    float t = fmaxf(x * 1.4426950409f, -120.f);
    float r = rintf(t);
    float f = t - r;
    float p = 1.33336e-3f;
    p = fmaf(p, f, 9.61812e-3f);
    p = fmaf(p, f, 5.55041e-2f);
    p = fmaf(p, f, 2.4022651e-1f);
    p = fmaf(p, f, 6.9314718e-1f);
    p = fmaf(p, f, 1.0f);
    return p * __int_as_float(((int)r + 127) << 23);
}

// ---------------- mask scan: compaction indices both directions ----------------
__global__ void scan_kernel(const unsigned char* __restrict__ m){
    __shared__ int anynz;
    __shared__ int sc[256];
    int tid = threadIdx.x, b = blockIdx.x;
    if (tid == 0) anynz = 0;
    __syncthreads();
    int loc = 0;
    for (int i = tid; i < 8192; i += 256)
        if ((i & 3) && m[i]) loc = 1;
    if (loc) atomicOr(&anynz, 1);
    __syncthreads();
    bool u8 = (anynz != 0);
    const int* mi = (const int*)m;

    int base = tid * 17, c = 0;
    unsigned int bits = 0;
    #pragma unroll
    for (int e = 0; e < 17; e++){
        int w = base + e;
        int on = 0;
        if (w < NK) on = u8 ? (m[b*NK + w] != 0) : (mi[b*NK + w] != 0);
        bits |= (unsigned)on << e;
        c += on;
    }
    sc[tid] = c;
    __syncthreads();
    for (int off = 1; off < 256; off <<= 1){
        int v = (tid >= off) ? sc[tid - off] : 0;
        __syncthreads();
        sc[tid] += v;
        __syncthreads();
    }
    int pos = sc[tid] - c;
    #pragma unroll
    for (int e = 0; e < 17; e++){
        int w = base + e;
        if (w < NKP){
            if ((bits >> e) & 1){
                g_gidx[b][pos] = w;
                g_scat[b*NKP + w] = pos;
                pos++;
            } else {
                g_scat[b*NKP + w] = -1;
            }
        }
    }
    if (tid == 255) g_nvalid[b] = sc[255];
}

// ---------------- pooled mean (two-phase, deterministic) ----------------
__global__ void pooled_p1(const float* __restrict__ x){
    int id = blockIdx.x*256 + threadIdx.x;
    int chunk = blockIdx.y;
    int b = id / QD, d = id % QD;
    const float* p = x + (size_t)b*N*QD + (size_t)chunk*256*QD + d;
    float s = 0.f;
    #pragma unroll 8
    for (int n = 0; n < 256; n++) s += p[(size_t)n*QD];
    g_ppart[chunk][id] = s;
}
__global__ void pooled_p2(){
    int id = blockIdx.x*256 + threadIdx.x;
    if (id >= B*QD) return;
    float s = 0.f;
    #pragma unroll
    for (int c = 0; c < 16; c++) s += g_ppart[c][id];
    g_pooled[id] = s * (1.0f/N);
}

__global__ void bg_kernel(const float* __restrict__ Wkbg, const float* __restrict__ Wvbg){
    int id = blockIdx.x*256 + threadIdx.x;
    if (id >= B*INNER) return;
    int b = id / INNER, o = id % INNER;
    float sk = 0.f, sv = 0.f;
    for (int k = 0; k < QD; k++){
        float pv = g_pooled[b*QD + k];
        sk += pv * Wkbg[(size_t)k*INNER + o];
        sv += pv * Wvbg[(size_t)k*INNER + o];
    }
    // v: full-order row N (for vtrans gather)
    size_t vb = (size_t)(b*NKP + N)*INNER + o;
    bf h;
    h = __float2bfloat16(sv); g_v[0][vb] = h; g_v[1][vb] = __float2bfloat16(sv - __bfloat162float(h));
    // k: dense slot (if bg key unmasked)
    int pos = g_scat[b*NKP + N];
    if (pos >= 0){
        size_t kb = (size_t)(b*NKP + pos)*INNER + o;
        h = __float2bfloat16(sk); g_kd[0][kb] = h; g_kd[1][kb] = __float2bfloat16(sk - __bfloat162float(h));
    }
}

__global__ void pack_split(const float4* __restrict__ src, bf* __restrict__ hi, bf* __restrict__ lo, int n4){
    int i = blockIdx.x*256 + threadIdx.x;
    if (i >= n4) return;
    float4 v = src[i];
    uint32_t h0 = packbf(v.x, v.y), h1 = packbf(v.z, v.w);
    uint32_t l0 = packbf_lo(v.x, v.y, h0), l1 = packbf_lo(v.z, v.w, h1);
    ((uint2*)hi)[i] = make_uint2(h0, h1);
    ((uint2*)lo)[i] = make_uint2(l0, l1);
}

__global__ void packT(const float* __restrict__ src, bf* __restrict__ hi, bf* __restrict__ lo, int R, int C){
    __shared__ float t[32][33];
    int c0 = blockIdx.x*32, r0 = blockIdx.y*32;
    for (int i = threadIdx.y; i < 32; i += 8)
        t[i][threadIdx.x] = src[(size_t)(r0+i)*C + c0 + threadIdx.x];
    __syncthreads();
    for (int i = threadIdx.y; i < 32; i += 8){
        float v = t[threadIdx.x][i];
        size_t o = (size_t)(c0+i)*R + r0 + threadIdx.x;
        bf h = __float2bfloat16(v);
        hi[o] = h; lo[o] = __float2bfloat16(v - __bfloat162float(h));
    }
}

// gather + transpose v into dense g_vt; zero tail (>= nvalid)
__global__ void vtrans_kernel(){
    __shared__ bf t[2][32][33];
    int z = blockIdx.z, b = z >> 3, h = z & 7;
    int j0 = blockIdx.x*32, d0 = blockIdx.y*32;
    int tx = threadIdx.x, ty = threadIdx.y;
    int nv = g_nvalid[b];
    #pragma unroll
    for (int s = 0; s < 2; s++)
        for (int i = ty; i < 32; i += 8){
            int jd = j0 + i;
            bf val = __float2bfloat16(0.f);
            if (jd < nv){
                int src = g_gidx[b][jd];
                val = g_v[s][(size_t)(b*NKP + src)*INNER + h*64 + d0 + tx];
            }
            t[s][i][tx] = val;
        }
    __syncthreads();
    #pragma unroll
    for (int s = 0; s < 2; s++)
        for (int i = ty; i < 32; i += 8)
            g_vt[s][((size_t)z*DH + d0 + i)*NKP + j0 + tx] = t[s][tx][i];
}

// ---------------- fused flash attention (fixed-shift softmax) ----------------
#define FSP 72
#define FTB (64*FSP*2)
#define FSTG (4*FTB)
#define FSMEM (2*FTB + 2*FSTG + 128)

__global__ __launch_bounds__(128, 2) void flash_kernel(){
    extern __shared__ __align__(16) char fsm[];
    const int tid = threadIdx.x, wid = tid >> 5, lane = tid & 31;
    const int z = blockIdx.y, b = z >> 3, h = z & 7;
    const int q0 = blockIdx.x*64;
    uint32_t sb = sm_u32(fsm);
    const uint32_t oQ = 0, oS = 2*FTB;

    const int nv = g_nvalid[b];
    const int ntiles = (nv + 63) >> 6;

    const bf* Qg[2] = { g_q[0] + ((size_t)(b*N + q0))*INNER + h*64,
                        g_q[1] + ((size_t)(b*N + q0))*INNER + h*64 };
    const bf* Kg[2] = { g_kd[0] + (size_t)b*NKP*INNER + h*64,
                        g_kd[1] + (size_t)b*NKP*INNER + h*64 };
    const bf* Vg[2] = { g_vt[0] + (size_t)z*DH*NKP,
                        g_vt[1] + (size_t)z*DH*NKP };

    auto load_stage = [&](int t){
        int j0 = t*64;
        uint32_t st = sb + oS + (t & 1)*FSTG;
        #pragma unroll 4
        for (int u = tid; u < 2048; u += 128){
            int tile = u >> 9, r = (u >> 3) & 63, sg = u & 7;
            const bf* src;
            if (tile == 0)      src = Kg[0] + (size_t)(j0 + r)*INNER + sg*8;
            else if (tile == 1) src = Kg[1] + (size_t)(j0 + r)*INNER + sg*8;
            else if (tile == 2) src = Vg[0] + (size_t)r*NKP + j0 + sg*8;
            else                src = Vg[1] + (size_t)r*NKP + j0 + sg*8;
            CP_ASYNC(st + tile*FTB + (uint32_t)(r*FSP + sg*8)*2, src);
        }
    };

    #pragma unroll 4
    for (int u = tid; u < 1024; u += 128){
        int half = u >> 9, r = (u >> 3) & 63, sg = u & 7;
        CP_ASYNC(sb + oQ + half*FTB + (uint32_t)(r*FSP + sg*8)*2,
                 Qg[half] + (size_t)r*INNER + sg*8);
    }
    if (ntiles > 0) load_stage(0);
    CP_COMMIT();
    if (ntiles > 1) load_stage(1);
    CP_COMMIT();

    uint32_t aQh[4][4], aQl[4][4];
    float lacc0 = 0.f, lacc1 = 0.f;
    float o[8][4];
    #pragma unroll
    for (int i = 0; i < 8; i++){ o[i][0]=0.f; o[i][1]=0.f; o[i][2]=0.f; o[i][3]=0.f; }

    const int gg = lane >> 3, ii = lane & 7, tq = lane & 3;

    for (int t = 0; t < ntiles; t++){
        if (t + 2 < ntiles) CP_WAIT1(); else CP_WAIT0();
        __syncthreads();

        if (t == 0){
            int row = wid*16 + (lane & 15);
            int col = (lane >> 4)*8;
            #pragma unroll
            for (int ks = 0; ks < 4; ks++){
                uint32_t ad = sb + oQ + (uint32_t)(row*FSP + ks*16 + col)*2;
                ldmx4(aQh[ks], ad);
                ldmx4(aQl[ks], ad + FTB);
            }
        }

        uint32_t st = sb + oS + (t & 1)*FSTG;

        float s[8][4];
        #pragma unroll
        for (int i = 0; i < 8; i++){ s[i][0]=0.f; s[i][1]=0.f; s[i][2]=0.f; s[i][3]=0.f; }
        #pragma unroll
        for (int ks = 0; ks < 4; ks++){
            #pragma unroll
            for (int p = 0; p < 4; p++){
                int rn = p*16 + (gg >> 1)*8 + ii;
                int ck = ks*16 + (gg & 1)*8;
                uint32_t off = (uint32_t)(rn*FSP + ck)*2;
                uint32_t bh[4], bl[4];
                ldmx4(bh, st + off);
                ldmx4(bl, st + FTB + off);
                mma16816(s[2*p],   aQh[ks], bh);
                mma16816(s[2*p],   aQh[ks], bl);
                mma16816(s[2*p],   aQl[ks], bh);
                mma16816(s[2*p+1], aQh[ks], bh + 2);
                mma16816(s[2*p+1], aQh[ks], bl + 2);
                mma16816(s[2*p+1], aQl[ks], bh + 2);
            }
        }

        // mask + scale + exp (no running max: scores bounded, shift-invariant)
        int jb = t*64;
        #pragma unroll
        for (int nt = 0; nt < 8; nt++){
            int c0 = jb + nt*8 + tq*2;
            bool k0 = c0 < nv, k1 = (c0 + 1) < nv;
            s[nt][0] = fexp(k0 ? s[nt][0]*0.125f : -1e30f);
            s[nt][1] = fexp(k1 ? s[nt][1]*0.125f : -1e30f);
            s[nt][2] = fexp(k0 ? s[nt][2]*0.125f : -1e30f);
            s[nt][3] = fexp(k1 ? s[nt][3]*0.125f : -1e30f);
            lacc0 += s[nt][0] + s[nt][1];
            lacc1 += s[nt][2] + s[nt][3];
        }

        // PV: O += Ph Vh + Ph Vl + Pl Vh
        #pragma unroll
        for (int ks = 0; ks < 4; ks++){
            uint32_t aPh[4], aPl[4];
            aPh[0] = packbf(s[2*ks][0],   s[2*ks][1]);
            aPh[1] = packbf(s[2*ks][2],   s[2*ks][3]);
            aPh[2] = packbf(s[2*ks+1][0], s[2*ks+1][1]);
            aPh[3] = packbf(s[2*ks+1][2], s[2*ks+1][3]);
            aPl[0] = packbf_lo(s[2*ks][0],   s[2*ks][1],   aPh[0]);
            aPl[1] = packbf_lo(s[2*ks][2],   s[2*ks][3],   aPh[1]);
            aPl[2] = packbf_lo(s[2*ks+1][0], s[2*ks+1][1], aPh[2]);
            aPl[3] = packbf_lo(s[2*ks+1][2], s[2*ks+1][3], aPh[3]);
            #pragma unroll
            for (int dp = 0; dp < 4; dp++){
                int rn = dp*16 + (gg >> 1)*8 + ii;
                int ck = ks*16 + (gg & 1)*8;
                uint32_t off = (uint32_t)(rn*FSP + ck)*2;
                uint32_t vh[4], vl[4];
                ldmx4(vh, st + 2*FTB + off);
                ldmx4(vl, st + 3*FTB + off);
                mma16816(o[2*dp],   aPh, vh);
                mma16816(o[2*dp],   aPh, vl);
                mma16816(o[2*dp],   aPl, vh);
                mma16816(o[2*dp+1], aPh, vh + 2);
                mma16816(o[2*dp+1], aPh, vl + 2);
                mma16816(o[2*dp+1], aPl, vh + 2);
            }
        }
        __syncthreads();
        if (t + 2 < ntiles){ load_stage(t + 2); CP_COMMIT(); }
    }

    // single final reduction of l over the 4 column-lanes
    lacc0 += __shfl_xor_sync(~0u, lacc0, 1); lacc0 += __shfl_xor_sync(~0u, lacc0, 2);
    lacc1 += __shfl_xor_sync(~0u, lacc1, 1); lacc1 += __shfl_xor_sync(~0u, lacc1, 2);
    float inv0 = 1.0f / lacc0, inv1 = 1.0f / lacc1;

    int g = lane >> 2;
    int row0 = q0 + wid*16 + g, row1 = row0 + 8;
    ll base0 = ((ll)(b*N) + row0)*INNER + h*64;
    ll base1 = ((ll)(b*N) + row1)*INNER + h*64;
    #pragma unroll
    for (int nt = 0; nt < 8; nt++){
        int c = nt*8 + tq*2;
        float v0 = o[nt][0]*inv0, v1 = o[nt][1]*inv0;
        float v2 = o[nt][2]*inv1, v3 = o[nt][3]*inv1;
        uint32_t h0 = packbf(v0, v1), l0p = packbf_lo(v0, v1, h0);
        uint32_t h1 = packbf(v2, v3), l1p = packbf_lo(v2, v3, h1);
        *(uint32_t*)(g_ao[0] + base0 + c) = h0;
        *(uint32_t*)(g_ao[1] + base0 + c) = l0p;
        *(uint32_t*)(g_ao[0] + base1 + c) = h1;
        *(uint32_t*)(g_ao[1] + base1 + c) = l1p;
    }
}

// ---------------- warp-mma split-bf16 GEMM ----------------
struct GemmArgs {
    const bf *Ah, *Al, *Bh, *Bl;
    int K, lda, ldb;
    ll sAb, sAh, sBb, sBh;
    float* Cf; const float* bias;
    bf *Ch, *Cl;
    ll sCb, sCh; int ldc, remap;
    const int* rowmap;          // optional: orig-row -> dense-row (-1 drop)
};

template<int NTILE>
__global__ __launch_bounds__(256, 1) void gemm_mma(GemmArgs g){
    constexpr int KC = 32, KPAD = 40;
    constexpr int WGM = (NTILE == 128) ? 2 : 4;
    constexpr int WGN = 8 / WGM;
    constexpr int WM = 128 / WGM;
    constexpr int WN = NTILE / WGN;
    constexpr int MT = WM / 16, NT = WN / 8;
    constexpr int ASZ = 128 * KPAD * 2;
    constexpr int BSZ = NTILE * KPAD * 2;
    constexpr int STAGE = 2*ASZ + 2*BSZ;
    constexpr int TOT = 1024 + NTILE*8;

    extern __shared__ __align__(16) char smem[];
    uint32_t sbase = sm_u32(smem);

    int tid = threadIdx.x, wid = tid >> 5, lane = tid & 31;
    int wm = wid % WGM, wn = wid / WGM;

    int zb = blockIdx.z >> 3, zh = blockIdx.z & 7;
    const bf* pAh = g.Ah + zb*g.sAb + zh*g.sAh + (ll)blockIdx.y*128*g.lda;
    const bf* pAl = g.Al + zb*g.sAb + zh*g.sAh + (ll)blockIdx.y*128*g.lda;
    const bf* pBh = g.Bh + zb*g.sBb + zh*g.sBh + (ll)blockIdx.x*NTILE*g.ldb;
    const bf* pBl = g.Bl + zb*g.sBb + zh*g.sBh + (ll)blockIdx.x*NTILE*g.ldb;

    float acc[MT][NT][4];
    #pragma unroll
    for (int i = 0; i < MT; i++)
        #pragma unroll
        for (int j = 0; j < NT; j++)
            #pragma unroll
            for (int e = 0; e < 4; e++) acc[i][j][e] = 0.f;

    int nch = g.K / KC;

    auto load_chunk = [&](int c){
        int s = c & 1, k0 = c * KC;
        uint32_t st = sbase + s*STAGE;
        #pragma unroll 2
        for (int u = tid; u < TOT; u += 256){
            const bf* src; uint32_t doff; int rel, ld;
            if (u < 512)              { rel = u;              src = pAh; doff = 0;         ld = g.lda; }
            else if (u < 1024)        { rel = u - 512;        src = pAl; doff = ASZ;       ld = g.lda; }
            else if (u < 1024+NTILE*4){ rel = u - 1024;       src = pBh; doff = 2*ASZ;     ld = g.ldb; }
            else                      { rel = u-1024-NTILE*4; src = pBl; doff = 2*ASZ+BSZ; ld = g.ldb; }
            int r = rel >> 2, sg = rel & 3;
            CP_ASYNC(st + doff + (uint32_t)(r*KPAD + sg*8)*2, src + (ll)r*ld + k0 + sg*8);
        }
        CP_COMMIT();
    };

    load_chunk(0);
    for (int c = 0; c < nch; c++){
        if (c + 1 < nch){ load_chunk(c + 1); CP_WAIT1(); }
        else            { CP_WAIT0(); }
        __syncthreads();

        uint32_t stg = sbase + (c & 1)*STAGE;
        #pragma unroll
        for (int ks = 0; ks < 2; ks++){
            int kb = ks * 16;
            uint32_t aH[MT][4], aL[MT][4];
            #pragma unroll
            for (int mt = 0; mt < MT; mt++){
                int row = wm*WM + mt*16 + (lane & 15);
                int col = kb + (lane >> 4)*8;
                uint32_t ad = stg + (uint32_t)(row*KPAD + col)*2;
                ldmx4(aH[mt], ad);
                ldmx4(aL[mt], ad + ASZ);
            }
            #pragma unroll
            for (int p = 0; p < NT/2; p++){
                int gg = lane >> 3, ii = lane & 7;
                int row = wn*WN + p*16 + (gg >> 1)*8 + ii;
                int col = kb + (gg & 1)*8;
                uint32_t bd = stg + 2*ASZ + (uint32_t)(row*KPAD + col)*2;
                uint32_t bH[4], bL[4];
                ldmx4(bH, bd);
                ldmx4(bL, bd + BSZ);
                #pragma unroll
                for (int mt = 0; mt < MT; mt++){
                    mma16816(acc[mt][2*p],   aH[mt], bH);
                    mma16816(acc[mt][2*p],   aH[mt], bL);
                    mma16816(acc[mt][2*p],   aL[mt], bH);
                    mma16816(acc[mt][2*p+1], aH[mt], bH + 2);
                    mma16816(acc[mt][2*p+1], aH[mt], bL + 2);
                    mma16816(acc[mt][2*p+1], aL[mt], bH + 2);
                }
            }
        }
        __syncthreads();
    }

    ll zoff = zb*g.sCb + zh*g.sCh;
    int ncb = blockIdx.x*NTILE + wn*WN;
    #pragma unroll
    for (int mt = 0; mt < MT; mt++){
        #pragma unroll
        for (int hf = 0; hf < 2; hf++){
            int row = blockIdx.y*128 + wm*WM + mt*16 + (lane >> 2) + hf*8;
            int rb = row >> 12, rw = row & 4095;
            bool wr = true;
            ll orow;
            if (g.rowmap){
                int pos = g.rowmap[rb*NKP + rw];
                wr = pos >= 0;
                orow = (ll)rb*g.remap + (pos < 0 ? 0 : pos);
            } else {
                orow = (ll)rb*g.remap + rw;
            }
            ll basei = zoff + orow*(ll)g.ldc + ncb;
            if (!wr) continue;
            #pragma unroll
            for (int nt = 0; nt < NT; nt++){
                int cl = nt*8 + (lane & 3)*2;
                float v0 = acc[mt][nt][hf*2], v1 = acc[mt][nt][hf*2+1];
                if (g.Cf){
                    if (g.bias){ v0 += g.bias[ncb + cl]; v1 += g.bias[ncb + cl + 1]; }
                    float2 f2; f2.x = v0; f2.y = v1;
                    *(float2*)(g.Cf + basei + cl) = f2;
                } else {
                    uint32_t hh = packbf(v0, v1);
                    uint32_t lo = packbf_lo(v0, v1, hh);
                    *(uint32_t*)(g.Ch + basei + cl) = hh;
                    *(uint32_t*)(g.Cl + basei + cl) = lo;
                }
            }
        }
    }
}

// ---------------- launch ----------------
extern "C" void kernel_launch(void* const* d_in, const int* in_sizes, int n_in,
                              void* d_out, int out_size){
    const float* x    = (const float*)d_in[0];
    const float* ctx  = (const float*)d_in[1];
    const unsigned char* mask = (const unsigned char*)d_in[2];
    const float* Wq   = (const float*)d_in[3];
    const float* Wk   = (const float*)d_in[4];
    const float* Wv   = (const float*)d_in[5];
    const float* Wkbg = (const float*)d_in[6];
    const float* Wvbg = (const float*)d_in[7];
    const float* Wout = (const float*)d_in[8];
    const float* bout = (const float*)d_in[9];
    float* out = (float*)d_out;

    bf *xs, *cs, *wq, *wk, *wv, *wo, *q, *kd, *v, *ao;
    int* scat;
    cudaGetSymbolAddress((void**)&xs, g_xs);
    cudaGetSymbolAddress((void**)&cs, g_cs);
    cudaGetSymbolAddress((void**)&wq, g_wq);
    cudaGetSymbolAddress((void**)&wk, g_wk);
    cudaGetSymbolAddress((void**)&wv, g_wv);
    cudaGetSymbolAddress((void**)&wo, g_wo);
    cudaGetSymbolAddress((void**)&q,  g_q);
    cudaGetSymbolAddress((void**)&kd, g_kd);
    cudaGetSymbolAddress((void**)&v,  g_v);
    cudaGetSymbolAddress((void**)&ao, g_ao);
    cudaGetSymbolAddress((void**)&scat, g_scat);
    const size_t XSZ = (size_t)B*N*QD, QSZ = (size_t)B*N*INNER;
    const size_t KSZ = (size_t)B*NKP*INNER;
    const size_t WSZ = (size_t)QD*INNER;

    const int SM128 = 2*(2*128*40*2 + 2*128*40*2);
    cudaFuncSetAttribute(gemm_mma<128>, cudaFuncAttributeMaxDynamicSharedMemorySize, SM128);
    cudaFuncSetAttribute(flash_kernel,  cudaFuncAttributeMaxDynamicSharedMemorySize, FSMEM);

    scan_kernel<<<B, 256>>>(mask);
    pooled_p1<<<dim3(B*QD/256, 16), 256>>>(x);
    pooled_p2<<<(B*QD + 255)/256, 256>>>();
    pack_split<<<(int)((XSZ/4 + 255)/256), 256>>>((const float4*)x,   xs, xs + XSZ, (int)(XSZ/4));
    pack_split<<<(int)((XSZ/4 + 255)/256), 256>>>((const float4*)ctx, cs, cs + XSZ, (int)(XSZ/4));
    packT<<<dim3(INNER/32, QD/32),    dim3(32, 8)>>>(Wq,   wq, wq + WSZ, QD, INNER);
    packT<<<dim3(INNER/32, QD/32),    dim3(32, 8)>>>(Wk,   wk, wk + WSZ, CD, INNER);
    packT<<<dim3(INNER/32, QD/32),    dim3(32, 8)>>>(Wv,   wv, wv + WSZ, CD, INNER);
    packT<<<dim3(QD/32,    INNER/32), dim3(32, 8)>>>(Wout, wo, wo + WSZ, INNER, QD);
    bg_kernel<<<(B*INNER + 255)/256, 256>>>(Wkbg, Wvbg);

    GemmArgs a;
    // q = x @ Wq
    a = { xs, xs + XSZ, wq, wq + WSZ, QD, QD, QD, 0, 0, 0, 0,
          nullptr, nullptr, q, q + QSZ, 0, 0, INNER, 4096, nullptr };
    gemm_mma<128><<<dim3(INNER/128, (B*N)/128, 1), 256, SM128>>>(a);
    // k = ctx @ Wk, scattered directly to dense key order
    a = { cs, cs + XSZ, wk, wk + WSZ, CD, CD, CD, 0, 0, 0, 0,
          nullptr, nullptr, kd, kd + KSZ, 0, 0, INNER, NKP, scat };
    gemm_mma<128><<<dim3(INNER/128, (B*N)/128, 1), 256, SM128>>>(a);
    // v = ctx @ Wv (full order, for gather-transpose)
    a = { cs, cs + XSZ, wv, wv + WSZ, CD, CD, CD, 0, 0, 0, 0,
          nullptr, nullptr, v, v + KSZ, 0, 0, INNER, NKP, nullptr };
    gemm_mma<128><<<dim3(INNER/128, (B*N)/128, 1), 256, SM128>>>(a);
    // vT (dense, transposed, zero tail)
    vtrans_kernel<<<dim3(NKP/32, DH/32, B*H), dim3(32, 8)>>>();
    // fused attention over dense keys
    flash_kernel<<<dim3(N/64, B*H), 128, FSMEM>>>();
    // out = ao @ Wout + b
    a = { ao, ao + QSZ, wo, wo + WSZ, INNER, INNER, INNER, 0, 0, 0, 0,
          out, bout, nullptr, nullptr, 0, 0, QD, 4096, nullptr };
    gemm_mma<128><<<dim3(QD/128, (B*N)/128, 1), 256, SM128>>>(a);
}